// round 9
// baseline (speedup 1.0000x reference)
#include <cuda_runtime.h>
#include <math.h>

// ---------------------------------------------------------------------------
// Problem constants (fixed shapes)
// ---------------------------------------------------------------------------
#define Bc   2
#define Nc   512
#define CSc  384
#define Hc   12
#define Cc   16
#define Pc   8
#define PVc  8
#define Kc   16
#define Gc   64
#define NTOK (Bc*Nc)          // 1024
#define SCALEF 0.1f
#define INFF   100000.0f

// scratch (device globals; no allocation allowed)
__device__ float d_q   [NTOK*Hc*Cc];      // 1024*192
__device__ float d_k   [NTOK*Hc*Cc];
__device__ float d_v   [NTOK*Hc*Cc];
__device__ float d_qpts[NTOK*Pc*3];       // 1024*24
__device__ float d_vpts[NTOK*Pc*3];
__device__ float d_kvp [NTOK*Hc*PVc*3];   // 1024*288
__device__ float d_vg  [NTOK*Hc*PVc*3];
__device__ float d_apre[(size_t)Bc*Nc*Hc*Nc]; // (b,i,h,j) 6.29M floats
__device__ float d_o   [NTOK*Hc*Cc];      // attention feature out
__device__ float d_opt [NTOK*Hc*PVc*3];   // attention point out (global frame)

// ---------------------------------------------------------------------------
// Kernel 1: per-token projections (8 tokens per block, register blocking)
// ---------------------------------------------------------------------------
__global__ void tok_kernel(
    const float* __restrict__ s_in,
    const float* __restrict__ ln_g, const float* __restrict__ ln_b,
    const float* __restrict__ Wq,   const float* __restrict__ bq,
    const float* __restrict__ Wkv,  const float* __restrict__ bkv,
    const float* __restrict__ Wpq,  const float* __restrict__ bpq,
    const float* __restrict__ Wpv,  const float* __restrict__ bpv,
    const float* __restrict__ Wkvp, const float* __restrict__ bkvp)
{
    __shared__ float s_s [8][CSc];
    __shared__ float sn_s[8][CSc];
    int t = threadIdx.x, wid = t >> 5, lane = t & 31;
    int tok0 = blockIdx.x * 8;

    for (int x = t; x < 8*CSc; x += 256) ((float*)s_s)[x] = s_in[tok0*CSc + x];
    __syncthreads();

    {
        float ps = 0.f, pq = 0.f;
        for (int kk = lane; kk < CSc; kk += 32) { float v = s_s[wid][kk]; ps += v; pq += v*v; }
        #pragma unroll
        for (int o = 16; o; o >>= 1) {
            ps += __shfl_xor_sync(0xffffffffu, ps, o);
            pq += __shfl_xor_sync(0xffffffffu, pq, o);
        }
        float mean = ps * (1.f/CSc);
        float var  = pq * (1.f/CSc) - mean*mean;
        float inv  = rsqrtf(var + 1e-5f);
        for (int kk = lane; kk < CSc; kk += 32)
            sn_s[wid][kk] = (s_s[wid][kk] - mean) * inv * ln_g[kk] + ln_b[kk];
    }
    __syncthreads();

    for (int idx = t; idx < 912; idx += 256) {
        const float *W, *bias, *src; float* dst; int outdim, col, dstride;
        if (idx < 192)      { col = idx;     W = Wq;   bias = bq;   outdim = 192; src = (const float*)s_s;  dst = d_q;    dstride = 192; }
        else if (idx < 576) { col = idx-192; W = Wkv;  bias = bkv;  outdim = 384; src = (const float*)s_s;  dst = 0;      dstride = 0;   }
        else if (idx < 600) { col = idx-576; W = Wpq;  bias = bpq;  outdim = 24;  src = (const float*)sn_s; dst = d_qpts; dstride = 24;  }
        else if (idx < 624) { col = idx-600; W = Wpv;  bias = bpv;  outdim = 24;  src = (const float*)sn_s; dst = d_vpts; dstride = 24;  }
        else                { col = idx-624; W = Wkvp; bias = bkvp; outdim = 288; src = (const float*)s_s;  dst = d_kvp;  dstride = 288; }
        float acc[8];
        float bv = bias[col];
        #pragma unroll
        for (int tt = 0; tt < 8; tt++) acc[tt] = bv;
        for (int kk = 0; kk < CSc; kk++) {
            float w = W[kk*outdim + col];
            #pragma unroll
            for (int tt = 0; tt < 8; tt++) acc[tt] += src[tt*CSc + kk] * w;
        }
        if (dst) {
            #pragma unroll
            for (int tt = 0; tt < 8; tt++) dst[(tok0+tt)*dstride + col] = acc[tt];
        } else {
            int h = col >> 5, cc = col & 31;
            if (cc < 16) { for (int tt = 0; tt < 8; tt++) d_k[(tok0+tt)*192 + h*16 + cc]      = acc[tt]; }
            else         { for (int tt = 0; tt < 8; tt++) d_v[(tok0+tt)*192 + h*16 + cc - 16] = acc[tt]; }
        }
    }
}

// ---------------------------------------------------------------------------
// Kernel 2: global value points  vg = R_j @ kv_pts + trans_j*SCALE
// ---------------------------------------------------------------------------
__global__ void vg_kernel(const float* __restrict__ rot, const float* __restrict__ trans)
{
    int idx = blockIdx.x*256 + threadIdx.x;
    if (idx >= NTOK*96) return;
    int tok = idx / 96, pidx = idx % 96;
    float p0 = d_kvp[tok*288 + pidx*3 + 0];
    float p1 = d_kvp[tok*288 + pidx*3 + 1];
    float p2 = d_kvp[tok*288 + pidx*3 + 2];
    const float* R = rot + tok*9;
    #pragma unroll
    for (int x = 0; x < 3; x++)
        d_vg[tok*288 + pidx*3 + x] =
            R[x*3+0]*p0 + R[x*3+1]*p1 + R[x*3+2]*p2 + trans[tok*3+x]*SCALEF;
}

// ---------------------------------------------------------------------------
// Kernel 3: qk GEMM — pre-writes qk*0.125 into d_apre
//   block = (itile64, h, b); C[64i,512j] = Q[64i,16] @ K[512j,16]^T
// ---------------------------------------------------------------------------
__global__ void qk_kernel()
{
    __shared__ float Q_s[64][17];
    __shared__ float K_s[64][17];
    int t = threadIdx.x;
    int i0 = blockIdx.x * 64, h = blockIdx.y, b = blockIdx.z;
    int jg = t & 15, ig = t >> 4;          // 16x16 thread grid, 4x4 outputs each

    for (int idx = t; idx < 64*16; idx += 256) {
        int r = idx >> 4, c = idx & 15;
        Q_s[r][c] = d_q[(b*512 + i0 + r)*192 + h*16 + c];
    }
    for (int jt = 0; jt < 8; jt++) {
        int j0 = jt * 64;
        __syncthreads();   // protect K_s from previous iter readers
        for (int idx = t; idx < 64*16; idx += 256) {
            int r = idx >> 4, c = idx & 15;
            K_s[r][c] = d_k[(b*512 + j0 + r)*192 + h*16 + c];
        }
        __syncthreads();
        float acc[4][4];
        #pragma unroll
        for (int a = 0; a < 4; a++)
            #pragma unroll
            for (int c = 0; c < 4; c++) acc[a][c] = 0.f;
        #pragma unroll
        for (int kk = 0; kk < 16; kk++) {
            float qv[4], kv[4];
            #pragma unroll
            for (int u = 0; u < 4; u++) { qv[u] = Q_s[ig*4+u][kk]; kv[u] = K_s[jg*4+u][kk]; }
            #pragma unroll
            for (int a = 0; a < 4; a++)
                #pragma unroll
                for (int c = 0; c < 4; c++) acc[a][c] += qv[a]*kv[c];
        }
        #pragma unroll
        for (int a = 0; a < 4; a++) {
            float4 v = make_float4(acc[a][0]*0.125f, acc[a][1]*0.125f,
                                   acc[a][2]*0.125f, acc[a][3]*0.125f);
            *(float4*)&d_apre[(((size_t)(b*512 + i0 + ig*4 + a))*12 + h)*512 + j0 + jg*4] = v;
        }
    }
}

// ---------------------------------------------------------------------------
// Kernel 4: pair kernel — one block per (b,i), 8 tiles of 64 j's
//   Weights Wg/W1 from GLOBAL (L1-cached); qk prevalue read from d_apre
// ---------------------------------------------------------------------------
// smem carve (floats)
#define SO_W2    0                      // [64][12]
#define SO_GAUSS (SO_W2   + 768)        // [64][132]
#define SO_G     (SO_GAUSS+ 8448)       // [64][68]
#define SO_H1    (SO_G    + 4352)       // [64][65]
#define SO_VLOC  (SO_H1   + 4160)       // [64][8][3]
#define SO_RT    (SO_VLOC + 1536)       // [64][12]
#define SO_PD    (SO_RT   + 768)        // 64
#define SO_MJ    (SO_PD   + 64)         // 64
#define SO_BG    (SO_MJ   + 64)         // 64
#define SO_B1    (SO_BG   + 64)         // 64
#define SO_B2    (SO_B1   + 64)         // 16
#define SO_HW    (SO_B2   + 16)         // 16
#define SO_WVL   (SO_HW   + 16)         // 128
#define SO_MEAN  (SO_WVL  + 128)        // 16
#define SO_ISTD  (SO_MEAN + 16)         // 16
#define SO_QP    (SO_ISTD + 16)         // 24
#define SO_RI    (SO_QP   + 24)         // 12
#define SO_TI    (SO_RI   + 12)         // 4
#define SO_MI    (SO_TI   + 4)          // 4
#define PAIR_SMEM_FLOATS (SO_MI + 4)
#define PAIR_SMEM_BYTES  (PAIR_SMEM_FLOATS*4)

__global__ void __launch_bounds__(256, 2) pair_kernel(
    const float* __restrict__ rot, const float* __restrict__ trans,
    const float* __restrict__ mask, const float* __restrict__ head_weights,
    const float* __restrict__ Wvl, const float* __restrict__ gbf_means,
    const float* __restrict__ gbf_stds,
    const float* __restrict__ Wg, const float* __restrict__ bg,
    const float* __restrict__ W1, const float* __restrict__ b1,
    const float* __restrict__ W2, const float* __restrict__ b2,
    float* __restrict__ out_g)
{
    extern __shared__ float sm[];
    float* W2_s   = sm + SO_W2;
    float* gauss_s= sm + SO_GAUSS;  // [j][132]
    float* g_s    = sm + SO_G;      // [j][68]
    float* h1_s   = sm + SO_H1;     // [j][65]
    float* vloc_s = sm + SO_VLOC;   // [j][8][3]
    float* RT_s   = sm + SO_RT;     // [j][12]
    float* pd_s   = sm + SO_PD;
    float* mj_s   = sm + SO_MJ;
    float* bg_s   = sm + SO_BG;
    float* b1_s   = sm + SO_B1;
    float* b2_s   = sm + SO_B2;
    float* hw_s   = sm + SO_HW;
    float* Wvl_s  = sm + SO_WVL;
    float* mean_s = sm + SO_MEAN;
    float* istd_s = sm + SO_ISTD;
    float* qpts_s = sm + SO_QP;
    float* Ri_s   = sm + SO_RI;
    float* ti_s   = sm + SO_TI;
    float* mi_s   = sm + SO_MI;

    int t = threadIdx.x;
    int toki = blockIdx.x;
    int b = toki >> 9;

    for (int x = t; x < 768;  x += 256) W2_s[x] = W2[x];
    if (t < 64) { bg_s[t] = bg[t]; b1_s[t] = b1[t]; }
    if (t < 12) {
        b2_s[t] = b2[t];
        float x = head_weights[t];
        float sp = (x > 20.f) ? x : log1pf(expf(x));
        hw_s[t] = sp * 0.23570226f * -0.5f;   // sqrt(1/(AFS*4.5)) * -0.5
    }
    if (t < 128) Wvl_s[t] = Wvl[t];
    if (t < 16) { mean_s[t] = gbf_means[t]; istd_s[t] = 1.f / gbf_stds[t]; }
    if (t < 24) qpts_s[t] = d_qpts[toki*24 + t];
    if (t < 9)  Ri_s[t]   = rot[toki*9 + t];
    if (t < 3)  ti_s[t]   = trans[toki*3 + t];
    if (t == 0) mi_s[0]   = mask[toki];
    __syncthreads();

    int og = t & 15, jg = t >> 4;       // register-tile coords for P4/P5
    int o0 = og * 4, j0r = jg * 4;

    for (int jt = 0; jt < 8; jt++) {
        int j0 = jt * 64;
        // ---- P1: per-j relative frame, pair_dist, mask ----
        if (t < 64) {
            int tokj = b*512 + j0 + t;
            float Rj[9], tj[3];
            #pragma unroll
            for (int x = 0; x < 9; x++) Rj[x] = rot[tokj*9 + x];
            #pragma unroll
            for (int x = 0; x < 3; x++) tj[x] = trans[tokj*3 + x];
            #pragma unroll
            for (int x = 0; x < 3; x++)
                #pragma unroll
                for (int z = 0; z < 3; z++)
                    RT_s[t*12 + x*3 + z] =
                        Ri_s[0*3+x]*Rj[0*3+z] + Ri_s[1*3+x]*Rj[1*3+z] + Ri_s[2*3+x]*Rj[2*3+z];
            float dt0 = tj[0]-ti_s[0], dt1 = tj[1]-ti_s[1], dt2 = tj[2]-ti_s[2];
            #pragma unroll
            for (int x = 0; x < 3; x++)
                RT_s[t*12 + 9 + x] = Ri_s[0*3+x]*dt0 + Ri_s[1*3+x]*dt1 + Ri_s[2*3+x]*dt2;
            pd_s[t] = (dt0*dt0 + dt1*dt1 + dt2*dt2) * (SCALEF*SCALEF);
            mj_s[t] = mask[tokj];
        }
        __syncthreads();

        // ---- P2: v_loc = Rrel @ v_pts_j + t_rel  (512 items, 2/thread) ----
        #pragma unroll
        for (int pass = 0; pass < 2; pass++) {
            int idx = t + pass*256;
            int jl = idx >> 3, p = idx & 7;
            int tokj = b*512 + j0 + jl;
            float vx = d_vpts[tokj*24 + p*3 + 0];
            float vy = d_vpts[tokj*24 + p*3 + 1];
            float vz = d_vpts[tokj*24 + p*3 + 2];
            const float* RT = RT_s + jl*12;
            #pragma unroll
            for (int x = 0; x < 3; x++)
                vloc_s[(jl*8+p)*3 + x] = RT[x*3+0]*vx + RT[x*3+1]*vy + RT[x*3+2]*vz + RT[9+x];
        }
        __syncthreads();

        // ---- P3: vec / vlen / gauss  (512 items, 2/thread) ----
        #pragma unroll
        for (int pass = 0; pass < 2; pass++) {
            int idx = t + pass*256;
            int jl = idx >> 3, o = idx & 7;
            float vec[3];
            #pragma unroll
            for (int c = 0; c < 3; c++) {
                float a = vloc_s[(jl*8+o)*3 + c];
                #pragma unroll
                for (int p = 0; p < 8; p++) {
                    a += Wvl_s[o*16 + p]     * vloc_s[(jl*8+p)*3 + c];
                    a += Wvl_s[o*16 + 8 + p] * qpts_s[p*3 + c];
                }
                vec[c] = a;
            }
            float vlen = sqrtf(vec[0]*vec[0] + vec[1]*vec[1] + vec[2]*vec[2] + 1e-8f);
            float gv[16];
            #pragma unroll
            for (int k = 0; k < 16; k++) {
                float zz = (vlen - mean_s[k]) * istd_s[k];
                gv[k] = __expf(-0.5f*zz*zz);
            }
            float* gp = gauss_s + jl*132 + o*16;
            #pragma unroll
            for (int k4 = 0; k4 < 4; k4++)
                *(float4*)&gp[k4*4] = make_float4(gv[k4*4], gv[k4*4+1], gv[k4*4+2], gv[k4*4+3]);
        }
        __syncthreads();

        // ---- P4: g = gauss @ Wg + bg  (4j x 4o per thread; Wg from L1) ----
        {
            float acc[4][4];
            #pragma unroll
            for (int jj = 0; jj < 4; jj++)
                #pragma unroll
                for (int u = 0; u < 4; u++) acc[jj][u] = bg_s[o0+u];
            const float* gp = gauss_s + j0r*132;
            #pragma unroll 4
            for (int kk = 0; kk < 128; kk++) {
                float a0 = gp[kk], a1 = gp[132+kk], a2 = gp[264+kk], a3 = gp[396+kk];
                float4 w = *(const float4*)&Wg[kk*64 + o0];
                acc[0][0] += a0*w.x; acc[0][1] += a0*w.y; acc[0][2] += a0*w.z; acc[0][3] += a0*w.w;
                acc[1][0] += a1*w.x; acc[1][1] += a1*w.y; acc[1][2] += a1*w.z; acc[1][3] += a1*w.w;
                acc[2][0] += a2*w.x; acc[2][1] += a2*w.y; acc[2][2] += a2*w.z; acc[2][3] += a2*w.w;
                acc[3][0] += a3*w.x; acc[3][1] += a3*w.y; acc[3][2] += a3*w.z; acc[3][3] += a3*w.w;
            }
            #pragma unroll
            for (int jj = 0; jj < 4; jj++) {
                float4 v = make_float4(acc[jj][0], acc[jj][1], acc[jj][2], acc[jj][3]);
                *(float4*)&g_s[(j0r+jj)*68 + o0] = v;
                *(float4*)&out_g[((size_t)toki*512 + (j0 + j0r + jj))*64 + o0] = v;
            }
        }
        __syncthreads();

        // ---- P5: h1 = relu(g @ W1 + b1)  (4j x 4o; W1 from L1) ----
        {
            float acc[4][4];
            #pragma unroll
            for (int jj = 0; jj < 4; jj++)
                #pragma unroll
                for (int u = 0; u < 4; u++) acc[jj][u] = b1_s[o0+u];
            const float* gp = g_s + j0r*68;
            #pragma unroll 4
            for (int kk = 0; kk < 64; kk++) {
                float a0 = gp[kk], a1 = gp[68+kk], a2 = gp[136+kk], a3 = gp[204+kk];
                float4 w = *(const float4*)&W1[kk*64 + o0];
                acc[0][0] += a0*w.x; acc[0][1] += a0*w.y; acc[0][2] += a0*w.z; acc[0][3] += a0*w.w;
                acc[1][0] += a1*w.x; acc[1][1] += a1*w.y; acc[1][2] += a1*w.z; acc[1][3] += a1*w.w;
                acc[2][0] += a2*w.x; acc[2][1] += a2*w.y; acc[2][2] += a2*w.z; acc[2][3] += a2*w.w;
                acc[3][0] += a3*w.x; acc[3][1] += a3*w.y; acc[3][2] += a3*w.z; acc[3][3] += a3*w.w;
            }
            #pragma unroll
            for (int jj = 0; jj < 4; jj++) {
                float* hp = &h1_s[(j0r+jj)*65 + o0];
                hp[0] = fmaxf(acc[jj][0], 0.f);
                hp[1] = fmaxf(acc[jj][1], 0.f);
                hp[2] = fmaxf(acc[jj][2], 0.f);
                hp[3] = fmaxf(acc[jj][3], 0.f);
            }
        }
        __syncthreads();

        // ---- P6: vfn = h1 @ W2 + b2 ; combine with pre-written qk ----
        #pragma unroll
        for (int pass = 0; pass < 3; pass++) {
            int idx = t + pass*256;
            int jl = idx & 63, h = idx >> 6;
            float a0 = 0.f, a1 = 0.f, a2 = 0.f, a3 = 0.f;
            const float* hh = h1_s + jl*65;
            const float* w2 = W2_s + h;
            #pragma unroll 4
            for (int kk = 0; kk < 64; kk += 4) {
                a0 += hh[kk]   * w2[kk*12];
                a1 += hh[kk+1] * w2[(kk+1)*12];
                a2 += hh[kk+2] * w2[(kk+2)*12];
                a3 += hh[kk+3] * w2[(kk+3)*12];
            }
            float acc = b2_s[h] + (a0+a1) + (a2+a3);
            int j = j0 + jl;
            size_t aidx = ((size_t)toki*12 + h)*512 + j;
            float pre = d_apre[aidx];   // qk*0.125 from qk_kernel (coalesced)
            float logit = pre + acc*0.5f + pd_s[jl]*hw_s[h]
                        + INFF*(mi_s[0]*mj_s[jl] - 1.0f);
            d_apre[aidx] = logit;
        }
        __syncthreads();
    }
}

// ---------------------------------------------------------------------------
// Kernel 5: softmax over j (in-place on d_apre), register-cached rows
// ---------------------------------------------------------------------------
__global__ void softmax_kernel()
{
    int toki = blockIdx.x;
    int t = threadIdx.x, wid = t >> 5, lane = t & 31;
    for (int h = wid; h < 12; h += 4) {
        float* row = d_apre + ((size_t)toki*12 + h)*512;
        float r[16];
        float m = -1e30f;
        #pragma unroll
        for (int kk = 0; kk < 16; kk++) { r[kk] = row[lane + kk*32]; m = fmaxf(m, r[kk]); }
        #pragma unroll
        for (int o = 16; o; o >>= 1) m = fmaxf(m, __shfl_xor_sync(0xffffffffu, m, o));
        float sum = 0.f;
        #pragma unroll
        for (int kk = 0; kk < 16; kk++) { r[kk] = __expf(r[kk] - m); sum += r[kk]; }
        #pragma unroll
        for (int o = 16; o; o >>= 1) sum += __shfl_xor_sync(0xffffffffu, sum, o);
        float inv = 1.f / sum;
        #pragma unroll
        for (int kk = 0; kk < 16; kk++) row[lane + kk*32] = r[kk] * inv;
    }
}

// ---------------------------------------------------------------------------
// Kernel 6: AV GEMM — per (b,h,itile64): C[64i][40s] = A[64i,512j] @ Vt[512j,40s]
// ---------------------------------------------------------------------------
__global__ void av_kernel()
{
    __shared__ float A_s[64][65];
    __shared__ float Vt_s[64][40];
    int t = threadIdx.x;
    int itile = blockIdx.x, h = blockIdx.y, b = blockIdx.z;
    int i0 = itile * 64;
    int il = t & 63, sg = t >> 6;

    float acc[10];
    #pragma unroll
    for (int u = 0; u < 10; u++) acc[u] = 0.f;

    for (int jtt = 0; jtt < 8; jtt++) {
        int j0 = jtt * 64;
        for (int idx = t; idx < 4096; idx += 256) {
            int rr = idx >> 6, cc = idx & 63;
            A_s[rr][cc] = d_apre[(((size_t)(b*512 + i0 + rr))*12 + h)*512 + j0 + cc];
        }
        for (int idx = t; idx < 2560; idx += 256) {
            int jj = idx / 40, ss = idx % 40;
            int tok = b*512 + j0 + jj;
            Vt_s[jj][ss] = (ss < 16) ? d_v[tok*192 + h*16 + ss]
                                     : d_vg[tok*288 + h*24 + (ss-16)];
        }
        __syncthreads();
        #pragma unroll 4
        for (int jj = 0; jj < 64; jj++) {
            float a = A_s[il][jj];
            #pragma unroll
            for (int u = 0; u < 10; u++) acc[u] += a * Vt_s[jj][sg*10 + u];
        }
        __syncthreads();
    }
    int tok = b*512 + i0 + il;
    #pragma unroll
    for (int u = 0; u < 10; u++) {
        int ss = sg*10 + u;
        if (ss < 16) d_o  [tok*192 + h*16 + ss]      = acc[u];
        else         d_opt[tok*288 + h*24 + (ss-16)] = acc[u];
    }
}

// ---------------------------------------------------------------------------
// Kernel 7: local transform + dists + final GEMM (16 tokens per block)
// ---------------------------------------------------------------------------
__global__ void final_kernel(
    const float* __restrict__ rot, const float* __restrict__ trans,
    const float* __restrict__ Wout, const float* __restrict__ bout,
    float* __restrict__ out_s)
{
    __shared__ float feats[16][577];
    int t = threadIdx.x;
    int tok0 = blockIdx.x * 16;

    for (int idx = t; idx < 16*192; idx += 256) {
        int tt = idx / 192, cc = idx % 192;
        feats[tt][cc] = d_o[(tok0+tt)*192 + cc];
    }
    for (int idx = t; idx < 16*96; idx += 256) {
        int tt = idx / 96, pp = idx % 96;
        int tok = tok0 + tt;
        float px = d_opt[tok*288 + pp*3 + 0] - trans[tok*3+0]*SCALEF;
        float py = d_opt[tok*288 + pp*3 + 1] - trans[tok*3+1]*SCALEF;
        float pz = d_opt[tok*288 + pp*3 + 2] - trans[tok*3+2]*SCALEF;
        const float* R = rot + tok*9;
        float lx = R[0]*px + R[3]*py + R[6]*pz;
        float ly = R[1]*px + R[4]*py + R[7]*pz;
        float lz = R[2]*px + R[5]*py + R[8]*pz;
        float d  = sqrtf(lx*lx + ly*ly + lz*lz + 1e-8f);
        feats[tt][192 + pp] = lx;
        feats[tt][288 + pp] = ly;
        feats[tt][384 + pp] = lz;
        feats[tt][480 + pp] = d;
    }
    __syncthreads();

    for (int o = t; o < 384; o += 256) {
        float acc[16];
        float bv = bout[o];
        #pragma unroll
        for (int tt = 0; tt < 16; tt++) acc[tt] = bv;
        for (int kk = 0; kk < 576; kk++) {
            float w = Wout[kk*384 + o];
            #pragma unroll
            for (int tt = 0; tt < 16; tt++) acc[tt] += feats[tt][kk] * w;
        }
        #pragma unroll
        for (int tt = 0; tt < 16; tt++) out_s[(size_t)(tok0+tt)*384 + o] = acc[tt];
    }
}

// ---------------------------------------------------------------------------
// launch
// ---------------------------------------------------------------------------
extern "C" void kernel_launch(void* const* d_in, const int* in_sizes, int n_in,
                              void* d_out, int out_size)
{
    const float* s     = (const float*)d_in[0];
    const float* rot   = (const float*)d_in[1];
    const float* trans = (const float*)d_in[2];
    const float* mask  = (const float*)d_in[3];
    const float* Wq    = (const float*)d_in[4];
    const float* bq    = (const float*)d_in[5];
    const float* Wkv   = (const float*)d_in[6];
    const float* bkv   = (const float*)d_in[7];
    const float* hwts  = (const float*)d_in[8];
    const float* ln_g  = (const float*)d_in[9];
    const float* ln_b  = (const float*)d_in[10];
    const float* Wpq   = (const float*)d_in[11];
    const float* bpq   = (const float*)d_in[12];
    const float* Wpv   = (const float*)d_in[13];
    const float* bpv   = (const float*)d_in[14];
    const float* Wvl   = (const float*)d_in[15];
    const float* gm    = (const float*)d_in[16];
    const float* gs    = (const float*)d_in[17];
    const float* Wg    = (const float*)d_in[18];
    const float* bg    = (const float*)d_in[19];
    const float* W1    = (const float*)d_in[20];
    const float* b1    = (const float*)d_in[21];
    const float* W2    = (const float*)d_in[22];
    const float* b2    = (const float*)d_in[23];
    const float* Wkvp  = (const float*)d_in[24];
    const float* bkvp  = (const float*)d_in[25];
    const float* Wout  = (const float*)d_in[26];
    const float* bout  = (const float*)d_in[27];

    float* out   = (float*)d_out;
    float* out_s = out;                                   // (B,N,CS)
    float* out_g = out + (size_t)Bc*Nc*CSc;               // (B,N,N,G)

    tok_kernel<<<NTOK/8, 256>>>(s, ln_g, ln_b, Wq, bq, Wkv, bkv,
                                Wpq, bpq, Wpv, bpv, Wkvp, bkvp);
    vg_kernel<<<(NTOK*96 + 255)/256, 256>>>(rot, trans);
    qk_kernel<<<dim3(8, 12, 2), 256>>>();

    cudaFuncSetAttribute(pair_kernel, cudaFuncAttributeMaxDynamicSharedMemorySize,
                         PAIR_SMEM_BYTES);
    pair_kernel<<<NTOK, 256, PAIR_SMEM_BYTES>>>(rot, trans, mask, hwts, Wvl, gm, gs,
                                                Wg, bg, W1, b1, W2, b2, out_g);
    softmax_kernel<<<NTOK, 128>>>();
    av_kernel<<<dim3(8, 12, 2), 256>>>();
    final_kernel<<<NTOK/16, 256>>>(rot, trans, Wout, bout, out_s);
}

// round 10
// speedup vs baseline: 1.0109x; 1.0109x over previous
#include <cuda_runtime.h>
#include <math.h>

// ---------------------------------------------------------------------------
// Problem constants (fixed shapes)
// ---------------------------------------------------------------------------
#define Bc   2
#define Nc   512
#define CSc  384
#define Hc   12
#define Cc   16
#define Pc   8
#define PVc  8
#define Kc   16
#define Gc   64
#define NTOK (Bc*Nc)          // 1024
#define SCALEF 0.1f
#define INFF   100000.0f

// scratch (device globals; no allocation allowed)
__device__ float d_q   [NTOK*Hc*Cc];      // 1024*192
__device__ float d_k   [NTOK*Hc*Cc];
__device__ float d_v   [NTOK*Hc*Cc];
__device__ float d_qpts[NTOK*Pc*3];       // 1024*24
__device__ float d_vpts[NTOK*Pc*3];
__device__ float d_kvp [NTOK*Hc*PVc*3];   // 1024*288
__device__ float d_vg  [NTOK*Hc*PVc*3];
__device__ float d_apre[(size_t)Bc*Nc*Hc*Nc]; // (b,i,h,j) 6.29M floats
__device__ float d_o   [NTOK*Hc*Cc];      // attention feature out
__device__ float d_opt [NTOK*Hc*PVc*3];   // attention point out (global frame)

// ---------------------------------------------------------------------------
// Kernel 1: per-token projections (8 tokens per block, register blocking)
// ---------------------------------------------------------------------------
__global__ void tok_kernel(
    const float* __restrict__ s_in,
    const float* __restrict__ ln_g, const float* __restrict__ ln_b,
    const float* __restrict__ Wq,   const float* __restrict__ bq,
    const float* __restrict__ Wkv,  const float* __restrict__ bkv,
    const float* __restrict__ Wpq,  const float* __restrict__ bpq,
    const float* __restrict__ Wpv,  const float* __restrict__ bpv,
    const float* __restrict__ Wkvp, const float* __restrict__ bkvp)
{
    __shared__ float s_s [8][CSc];
    __shared__ float sn_s[8][CSc];
    int t = threadIdx.x, wid = t >> 5, lane = t & 31;
    int tok0 = blockIdx.x * 8;

    for (int x = t; x < 8*CSc; x += 256) ((float*)s_s)[x] = s_in[tok0*CSc + x];
    __syncthreads();

    {
        float ps = 0.f, pq = 0.f;
        for (int kk = lane; kk < CSc; kk += 32) { float v = s_s[wid][kk]; ps += v; pq += v*v; }
        #pragma unroll
        for (int o = 16; o; o >>= 1) {
            ps += __shfl_xor_sync(0xffffffffu, ps, o);
            pq += __shfl_xor_sync(0xffffffffu, pq, o);
        }
        float mean = ps * (1.f/CSc);
        float var  = pq * (1.f/CSc) - mean*mean;
        float inv  = rsqrtf(var + 1e-5f);
        for (int kk = lane; kk < CSc; kk += 32)
            sn_s[wid][kk] = (s_s[wid][kk] - mean) * inv * ln_g[kk] + ln_b[kk];
    }
    __syncthreads();

    for (int idx = t; idx < 912; idx += 256) {
        const float *W, *bias, *src; float* dst; int outdim, col, dstride;
        if (idx < 192)      { col = idx;     W = Wq;   bias = bq;   outdim = 192; src = (const float*)s_s;  dst = d_q;    dstride = 192; }
        else if (idx < 576) { col = idx-192; W = Wkv;  bias = bkv;  outdim = 384; src = (const float*)s_s;  dst = 0;      dstride = 0;   }
        else if (idx < 600) { col = idx-576; W = Wpq;  bias = bpq;  outdim = 24;  src = (const float*)sn_s; dst = d_qpts; dstride = 24;  }
        else if (idx < 624) { col = idx-600; W = Wpv;  bias = bpv;  outdim = 24;  src = (const float*)sn_s; dst = d_vpts; dstride = 24;  }
        else                { col = idx-624; W = Wkvp; bias = bkvp; outdim = 288; src = (const float*)s_s;  dst = d_kvp;  dstride = 288; }
        float acc[8];
        float bv = bias[col];
        #pragma unroll
        for (int tt = 0; tt < 8; tt++) acc[tt] = bv;
        for (int kk = 0; kk < CSc; kk++) {
            float w = W[kk*outdim + col];
            #pragma unroll
            for (int tt = 0; tt < 8; tt++) acc[tt] += src[tt*CSc + kk] * w;
        }
        if (dst) {
            #pragma unroll
            for (int tt = 0; tt < 8; tt++) dst[(tok0+tt)*dstride + col] = acc[tt];
        } else {
            int h = col >> 5, cc = col & 31;
            if (cc < 16) { for (int tt = 0; tt < 8; tt++) d_k[(tok0+tt)*192 + h*16 + cc]      = acc[tt]; }
            else         { for (int tt = 0; tt < 8; tt++) d_v[(tok0+tt)*192 + h*16 + cc - 16] = acc[tt]; }
        }
    }
}

// ---------------------------------------------------------------------------
// Kernel 2: global value points  vg = R_j @ kv_pts + trans_j*SCALE
// ---------------------------------------------------------------------------
__global__ void vg_kernel(const float* __restrict__ rot, const float* __restrict__ trans)
{
    int idx = blockIdx.x*256 + threadIdx.x;
    if (idx >= NTOK*96) return;
    int tok = idx / 96, pidx = idx % 96;
    float p0 = d_kvp[tok*288 + pidx*3 + 0];
    float p1 = d_kvp[tok*288 + pidx*3 + 1];
    float p2 = d_kvp[tok*288 + pidx*3 + 2];
    const float* R = rot + tok*9;
    #pragma unroll
    for (int x = 0; x < 3; x++)
        d_vg[tok*288 + pidx*3 + x] =
            R[x*3+0]*p0 + R[x*3+1]*p1 + R[x*3+2]*p2 + trans[tok*3+x]*SCALEF;
}

// ---------------------------------------------------------------------------
// Kernel 3: qk GEMM — pre-writes qk*0.125 into d_apre
//   block = (itile64, h, b); C[64i,512j] = Q[64i,16] @ K[512j,16]^T
// ---------------------------------------------------------------------------
__global__ void qk_kernel()
{
    __shared__ float Q_s[64][17];
    __shared__ float K_s[64][17];
    int t = threadIdx.x;
    int i0 = blockIdx.x * 64, h = blockIdx.y, b = blockIdx.z;
    int jg = t & 15, ig = t >> 4;          // 16x16 thread grid, 4x4 outputs each

    for (int idx = t; idx < 64*16; idx += 256) {
        int r = idx >> 4, c = idx & 15;
        Q_s[r][c] = d_q[(b*512 + i0 + r)*192 + h*16 + c];
    }
    for (int jt = 0; jt < 8; jt++) {
        int j0 = jt * 64;
        __syncthreads();   // protect K_s from previous iter readers
        for (int idx = t; idx < 64*16; idx += 256) {
            int r = idx >> 4, c = idx & 15;
            K_s[r][c] = d_k[(b*512 + j0 + r)*192 + h*16 + c];
        }
        __syncthreads();
        float acc[4][4];
        #pragma unroll
        for (int a = 0; a < 4; a++)
            #pragma unroll
            for (int c = 0; c < 4; c++) acc[a][c] = 0.f;
        #pragma unroll
        for (int kk = 0; kk < 16; kk++) {
            float qv[4], kv[4];
            #pragma unroll
            for (int u = 0; u < 4; u++) { qv[u] = Q_s[ig*4+u][kk]; kv[u] = K_s[jg*4+u][kk]; }
            #pragma unroll
            for (int a = 0; a < 4; a++)
                #pragma unroll
                for (int c = 0; c < 4; c++) acc[a][c] += qv[a]*kv[c];
        }
        #pragma unroll
        for (int a = 0; a < 4; a++) {
            float4 v = make_float4(acc[a][0]*0.125f, acc[a][1]*0.125f,
                                   acc[a][2]*0.125f, acc[a][3]*0.125f);
            *(float4*)&d_apre[(((size_t)(b*512 + i0 + ig*4 + a))*12 + h)*512 + j0 + jg*4] = v;
        }
    }
}

// ---------------------------------------------------------------------------
// Kernel 4: pair kernel — one block per (b,i), 8 tiles of 64 j's
//   Weights Wg/W1 from GLOBAL (L1-cached); qk prevalue read from d_apre
// ---------------------------------------------------------------------------
// smem carve (floats)
#define SO_W2    0                      // [64][12]
#define SO_GAUSS (SO_W2   + 768)        // [64][132]
#define SO_G     (SO_GAUSS+ 8448)       // [64][68]
#define SO_H1    (SO_G    + 4352)       // [64][65]
#define SO_VLOC  (SO_H1   + 4160)       // [64][8][3]
#define SO_RT    (SO_VLOC + 1536)       // [64][12]
#define SO_PD    (SO_RT   + 768)        // 64
#define SO_MJ    (SO_PD   + 64)         // 64
#define SO_BG    (SO_MJ   + 64)         // 64
#define SO_B1    (SO_BG   + 64)         // 64
#define SO_B2    (SO_B1   + 64)         // 16
#define SO_HW    (SO_B2   + 16)         // 16
#define SO_WVL   (SO_HW   + 16)         // 128
#define SO_MEAN  (SO_WVL  + 128)        // 16
#define SO_ISTD  (SO_MEAN + 16)         // 16
#define SO_QP    (SO_ISTD + 16)         // 24
#define SO_RI    (SO_QP   + 24)         // 12
#define SO_TI    (SO_RI   + 12)         // 4
#define SO_MI    (SO_TI   + 4)          // 4
#define PAIR_SMEM_FLOATS (SO_MI + 4)
#define PAIR_SMEM_BYTES  (PAIR_SMEM_FLOATS*4)

__global__ void __launch_bounds__(256, 2) pair_kernel(
    const float* __restrict__ rot, const float* __restrict__ trans,
    const float* __restrict__ mask, const float* __restrict__ head_weights,
    const float* __restrict__ Wvl, const float* __restrict__ gbf_means,
    const float* __restrict__ gbf_stds,
    const float* __restrict__ Wg, const float* __restrict__ bg,
    const float* __restrict__ W1, const float* __restrict__ b1,
    const float* __restrict__ W2, const float* __restrict__ b2,
    float* __restrict__ out_g)
{
    extern __shared__ float sm[];
    float* W2_s   = sm + SO_W2;
    float* gauss_s= sm + SO_GAUSS;  // [j][132]
    float* g_s    = sm + SO_G;      // [j][68]
    float* h1_s   = sm + SO_H1;     // [j][65]
    float* vloc_s = sm + SO_VLOC;   // [j][8][3]
    float* RT_s   = sm + SO_RT;     // [j][12]
    float* pd_s   = sm + SO_PD;
    float* mj_s   = sm + SO_MJ;
    float* bg_s   = sm + SO_BG;
    float* b1_s   = sm + SO_B1;
    float* b2_s   = sm + SO_B2;
    float* hw_s   = sm + SO_HW;
    float* Wvl_s  = sm + SO_WVL;
    float* mean_s = sm + SO_MEAN;
    float* istd_s = sm + SO_ISTD;
    float* qpts_s = sm + SO_QP;
    float* Ri_s   = sm + SO_RI;
    float* ti_s   = sm + SO_TI;
    float* mi_s   = sm + SO_MI;

    int t = threadIdx.x;
    int toki = blockIdx.x;
    int b = toki >> 9;

    for (int x = t; x < 768;  x += 256) W2_s[x] = W2[x];
    if (t < 64) { bg_s[t] = bg[t]; b1_s[t] = b1[t]; }
    if (t < 12) {
        b2_s[t] = b2[t];
        float x = head_weights[t];
        float sp = (x > 20.f) ? x : log1pf(expf(x));
        hw_s[t] = sp * 0.23570226f * -0.5f;   // sqrt(1/(AFS*4.5)) * -0.5
    }
    if (t < 128) Wvl_s[t] = Wvl[t];
    if (t < 16) { mean_s[t] = gbf_means[t]; istd_s[t] = 1.f / gbf_stds[t]; }
    if (t < 24) qpts_s[t] = d_qpts[toki*24 + t];
    if (t < 9)  Ri_s[t]   = rot[toki*9 + t];
    if (t < 3)  ti_s[t]   = trans[toki*3 + t];
    if (t == 0) mi_s[0]   = mask[toki];
    __syncthreads();

    int og = t & 15, jg = t >> 4;       // register-tile coords for P4/P5
    int o0 = og * 4, j0r = jg * 4;

    for (int jt = 0; jt < 8; jt++) {
        int j0 = jt * 64;
        // ---- P1: per-j relative frame, pair_dist, mask ----
        if (t < 64) {
            int tokj = b*512 + j0 + t;
            float Rj[9], tj[3];
            #pragma unroll
            for (int x = 0; x < 9; x++) Rj[x] = rot[tokj*9 + x];
            #pragma unroll
            for (int x = 0; x < 3; x++) tj[x] = trans[tokj*3 + x];
            #pragma unroll
            for (int x = 0; x < 3; x++)
                #pragma unroll
                for (int z = 0; z < 3; z++)
                    RT_s[t*12 + x*3 + z] =
                        Ri_s[0*3+x]*Rj[0*3+z] + Ri_s[1*3+x]*Rj[1*3+z] + Ri_s[2*3+x]*Rj[2*3+z];
            float dt0 = tj[0]-ti_s[0], dt1 = tj[1]-ti_s[1], dt2 = tj[2]-ti_s[2];
            #pragma unroll
            for (int x = 0; x < 3; x++)
                RT_s[t*12 + 9 + x] = Ri_s[0*3+x]*dt0 + Ri_s[1*3+x]*dt1 + Ri_s[2*3+x]*dt2;
            pd_s[t] = (dt0*dt0 + dt1*dt1 + dt2*dt2) * (SCALEF*SCALEF);
            mj_s[t] = mask[tokj];
        }
        __syncthreads();

        // ---- P2: v_loc = Rrel @ v_pts_j + t_rel  (512 items, 2/thread) ----
        #pragma unroll
        for (int pass = 0; pass < 2; pass++) {
            int idx = t + pass*256;
            int jl = idx >> 3, p = idx & 7;
            int tokj = b*512 + j0 + jl;
            float vx = d_vpts[tokj*24 + p*3 + 0];
            float vy = d_vpts[tokj*24 + p*3 + 1];
            float vz = d_vpts[tokj*24 + p*3 + 2];
            const float* RT = RT_s + jl*12;
            #pragma unroll
            for (int x = 0; x < 3; x++)
                vloc_s[(jl*8+p)*3 + x] = RT[x*3+0]*vx + RT[x*3+1]*vy + RT[x*3+2]*vz + RT[9+x];
        }
        __syncthreads();

        // ---- P3: vec / vlen / gauss  (512 items, 2/thread) ----
        #pragma unroll
        for (int pass = 0; pass < 2; pass++) {
            int idx = t + pass*256;
            int jl = idx >> 3, o = idx & 7;
            float vec[3];
            #pragma unroll
            for (int c = 0; c < 3; c++) {
                float a = vloc_s[(jl*8+o)*3 + c];
                #pragma unroll
                for (int p = 0; p < 8; p++) {
                    a += Wvl_s[o*16 + p]     * vloc_s[(jl*8+p)*3 + c];
                    a += Wvl_s[o*16 + 8 + p] * qpts_s[p*3 + c];
                }
                vec[c] = a;
            }
            float vlen = sqrtf(vec[0]*vec[0] + vec[1]*vec[1] + vec[2]*vec[2] + 1e-8f);
            float gv[16];
            #pragma unroll
            for (int k = 0; k < 16; k++) {
                float zz = (vlen - mean_s[k]) * istd_s[k];
                gv[k] = __expf(-0.5f*zz*zz);
            }
            float* gp = gauss_s + jl*132 + o*16;
            #pragma unroll
            for (int k4 = 0; k4 < 4; k4++)
                *(float4*)&gp[k4*4] = make_float4(gv[k4*4], gv[k4*4+1], gv[k4*4+2], gv[k4*4+3]);
        }
        __syncthreads();

        // ---- P4: g = gauss @ Wg + bg  (4j x 4o per thread; Wg from L1) ----
        {
            float acc[4][4];
            #pragma unroll
            for (int jj = 0; jj < 4; jj++)
                #pragma unroll
                for (int u = 0; u < 4; u++) acc[jj][u] = bg_s[o0+u];
            const float* gp = gauss_s + j0r*132;
            #pragma unroll 4
            for (int kk = 0; kk < 128; kk++) {
                float a0 = gp[kk], a1 = gp[132+kk], a2 = gp[264+kk], a3 = gp[396+kk];
                float4 w = *(const float4*)&Wg[kk*64 + o0];
                acc[0][0] += a0*w.x; acc[0][1] += a0*w.y; acc[0][2] += a0*w.z; acc[0][3] += a0*w.w;
                acc[1][0] += a1*w.x; acc[1][1] += a1*w.y; acc[1][2] += a1*w.z; acc[1][3] += a1*w.w;
                acc[2][0] += a2*w.x; acc[2][1] += a2*w.y; acc[2][2] += a2*w.z; acc[2][3] += a2*w.w;
                acc[3][0] += a3*w.x; acc[3][1] += a3*w.y; acc[3][2] += a3*w.z; acc[3][3] += a3*w.w;
            }
            #pragma unroll
            for (int jj = 0; jj < 4; jj++) {
                float4 v = make_float4(acc[jj][0], acc[jj][1], acc[jj][2], acc[jj][3]);
                *(float4*)&g_s[(j0r+jj)*68 + o0] = v;
                *(float4*)&out_g[((size_t)toki*512 + (j0 + j0r + jj))*64 + o0] = v;
            }
        }
        __syncthreads();

        // ---- P5: h1 = relu(g @ W1 + b1)  (4j x 4o; W1 from L1) ----
        {
            float acc[4][4];
            #pragma unroll
            for (int jj = 0; jj < 4; jj++)
                #pragma unroll
                for (int u = 0; u < 4; u++) acc[jj][u] = b1_s[o0+u];
            const float* gp = g_s + j0r*68;
            #pragma unroll 4
            for (int kk = 0; kk < 64; kk++) {
                float a0 = gp[kk], a1 = gp[68+kk], a2 = gp[136+kk], a3 = gp[204+kk];
                float4 w = *(const float4*)&W1[kk*64 + o0];
                acc[0][0] += a0*w.x; acc[0][1] += a0*w.y; acc[0][2] += a0*w.z; acc[0][3] += a0*w.w;
                acc[1][0] += a1*w.x; acc[1][1] += a1*w.y; acc[1][2] += a1*w.z; acc[1][3] += a1*w.w;
                acc[2][0] += a2*w.x; acc[2][1] += a2*w.y; acc[2][2] += a2*w.z; acc[2][3] += a2*w.w;
                acc[3][0] += a3*w.x; acc[3][1] += a3*w.y; acc[3][2] += a3*w.z; acc[3][3] += a3*w.w;
            }
            #pragma unroll
            for (int jj = 0; jj < 4; jj++) {
                float* hp = &h1_s[(j0r+jj)*65 + o0];
                hp[0] = fmaxf(acc[jj][0], 0.f);
                hp[1] = fmaxf(acc[jj][1], 0.f);
                hp[2] = fmaxf(acc[jj][2], 0.f);
                hp[3] = fmaxf(acc[jj][3], 0.f);
            }
        }
        __syncthreads();

        // ---- P6: vfn = h1 @ W2 + b2 ; combine with pre-written qk ----
        #pragma unroll
        for (int pass = 0; pass < 3; pass++) {
            int idx = t + pass*256;
            int jl = idx & 63, h = idx >> 6;
            float a0 = 0.f, a1 = 0.f, a2 = 0.f, a3 = 0.f;
            const float* hh = h1_s + jl*65;
            const float* w2 = W2_s + h;
            #pragma unroll 4
            for (int kk = 0; kk < 64; kk += 4) {
                a0 += hh[kk]   * w2[kk*12];
                a1 += hh[kk+1] * w2[(kk+1)*12];
                a2 += hh[kk+2] * w2[(kk+2)*12];
                a3 += hh[kk+3] * w2[(kk+3)*12];
            }
            float acc = b2_s[h] + (a0+a1) + (a2+a3);
            int j = j0 + jl;
            size_t aidx = ((size_t)toki*12 + h)*512 + j;
            float pre = d_apre[aidx];   // qk*0.125 from qk_kernel (coalesced)
            float logit = pre + acc*0.5f + pd_s[jl]*hw_s[h]
                        + INFF*(mi_s[0]*mj_s[jl] - 1.0f);
            d_apre[aidx] = logit;
        }
        __syncthreads();
    }
}

// ---------------------------------------------------------------------------
// Kernel 5: softmax over j (in-place on d_apre), register-cached rows
// ---------------------------------------------------------------------------
__global__ void softmax_kernel()
{
    int toki = blockIdx.x;
    int t = threadIdx.x, wid = t >> 5, lane = t & 31;
    for (int h = wid; h < 12; h += 4) {
        float* row = d_apre + ((size_t)toki*12 + h)*512;
        float r[16];
        float m = -1e30f;
        #pragma unroll
        for (int kk = 0; kk < 16; kk++) { r[kk] = row[lane + kk*32]; m = fmaxf(m, r[kk]); }
        #pragma unroll
        for (int o = 16; o; o >>= 1) m = fmaxf(m, __shfl_xor_sync(0xffffffffu, m, o));
        float sum = 0.f;
        #pragma unroll
        for (int kk = 0; kk < 16; kk++) { r[kk] = __expf(r[kk] - m); sum += r[kk]; }
        #pragma unroll
        for (int o = 16; o; o >>= 1) sum += __shfl_xor_sync(0xffffffffu, sum, o);
        float inv = 1.f / sum;
        #pragma unroll
        for (int kk = 0; kk < 16; kk++) row[lane + kk*32] = r[kk] * inv;
    }
}

// ---------------------------------------------------------------------------
// Kernel 6: AV GEMM — per (b,h,itile64): C[64i][40s] = A[64i,512j] @ Vt[512j,40s]
// ---------------------------------------------------------------------------
__global__ void av_kernel()
{
    __shared__ float A_s[64][65];
    __shared__ float Vt_s[64][40];
    int t = threadIdx.x;
    int itile = blockIdx.x, h = blockIdx.y, b = blockIdx.z;
    int i0 = itile * 64;
    int il = t & 63, sg = t >> 6;

    float acc[10];
    #pragma unroll
    for (int u = 0; u < 10; u++) acc[u] = 0.f;

    for (int jtt = 0; jtt < 8; jtt++) {
        int j0 = jtt * 64;
        for (int idx = t; idx < 4096; idx += 256) {
            int rr = idx >> 6, cc = idx & 63;
            A_s[rr][cc] = d_apre[(((size_t)(b*512 + i0 + rr))*12 + h)*512 + j0 + cc];
        }
        for (int idx = t; idx < 2560; idx += 256) {
            int jj = idx / 40, ss = idx % 40;
            int tok = b*512 + j0 + jj;
            Vt_s[jj][ss] = (ss < 16) ? d_v[tok*192 + h*16 + ss]
                                     : d_vg[tok*288 + h*24 + (ss-16)];
        }
        __syncthreads();
        #pragma unroll 4
        for (int jj = 0; jj < 64; jj++) {
            float a = A_s[il][jj];
            #pragma unroll
            for (int u = 0; u < 10; u++) acc[u] += a * Vt_s[jj][sg*10 + u];
        }
        __syncthreads();
    }
    int tok = b*512 + i0 + il;
    #pragma unroll
    for (int u = 0; u < 10; u++) {
        int ss = sg*10 + u;
        if (ss < 16) d_o  [tok*192 + h*16 + ss]      = acc[u];
        else         d_opt[tok*288 + h*24 + (ss-16)] = acc[u];
    }
}

// ---------------------------------------------------------------------------
// Kernel 7: local transform + dists + final GEMM (16 tokens per block)
// ---------------------------------------------------------------------------
__global__ void final_kernel(
    const float* __restrict__ rot, const float* __restrict__ trans,
    const float* __restrict__ Wout, const float* __restrict__ bout,
    float* __restrict__ out_s)
{
    __shared__ float feats[16][577];
    int t = threadIdx.x;
    int tok0 = blockIdx.x * 16;

    for (int idx = t; idx < 16*192; idx += 256) {
        int tt = idx / 192, cc = idx % 192;
        feats[tt][cc] = d_o[(tok0+tt)*192 + cc];
    }
    for (int idx = t; idx < 16*96; idx += 256) {
        int tt = idx / 96, pp = idx % 96;
        int tok = tok0 + tt;
        float px = d_opt[tok*288 + pp*3 + 0] - trans[tok*3+0]*SCALEF;
        float py = d_opt[tok*288 + pp*3 + 1] - trans[tok*3+1]*SCALEF;
        float pz = d_opt[tok*288 + pp*3 + 2] - trans[tok*3+2]*SCALEF;
        const float* R = rot + tok*9;
        float lx = R[0]*px + R[3]*py + R[6]*pz;
        float ly = R[1]*px + R[4]*py + R[7]*pz;
        float lz = R[2]*px + R[5]*py + R[8]*pz;
        float d  = sqrtf(lx*lx + ly*ly + lz*lz + 1e-8f);
        feats[tt][192 + pp] = lx;
        feats[tt][288 + pp] = ly;
        feats[tt][384 + pp] = lz;
        feats[tt][480 + pp] = d;
    }
    __syncthreads();

    for (int o = t; o < 384; o += 256) {
        float acc[16];
        float bv = bout[o];
        #pragma unroll
        for (int tt = 0; tt < 16; tt++) acc[tt] = bv;
        for (int kk = 0; kk < 576; kk++) {
            float w = Wout[kk*384 + o];
            #pragma unroll
            for (int tt = 0; tt < 16; tt++) acc[tt] += feats[tt][kk] * w;
        }
        #pragma unroll
        for (int tt = 0; tt < 16; tt++) out_s[(size_t)(tok0+tt)*384 + o] = acc[tt];
    }
}

// ---------------------------------------------------------------------------
// launch
// ---------------------------------------------------------------------------
extern "C" void kernel_launch(void* const* d_in, const int* in_sizes, int n_in,
                              void* d_out, int out_size)
{
    const float* s     = (const float*)d_in[0];
    const float* rot   = (const float*)d_in[1];
    const float* trans = (const float*)d_in[2];
    const float* mask  = (const float*)d_in[3];
    const float* Wq    = (const float*)d_in[4];
    const float* bq    = (const float*)d_in[5];
    const float* Wkv   = (const float*)d_in[6];
    const float* bkv   = (const float*)d_in[7];
    const float* hwts  = (const float*)d_in[8];
    const float* ln_g  = (const float*)d_in[9];
    const float* ln_b  = (const float*)d_in[10];
    const float* Wpq   = (const float*)d_in[11];
    const float* bpq   = (const float*)d_in[12];
    const float* Wpv   = (const float*)d_in[13];
    const float* bpv   = (const float*)d_in[14];
    const float* Wvl   = (const float*)d_in[15];
    const float* gm    = (const float*)d_in[16];
    const float* gs    = (const float*)d_in[17];
    const float* Wg    = (const float*)d_in[18];
    const float* bg    = (const float*)d_in[19];
    const float* W1    = (const float*)d_in[20];
    const float* b1    = (const float*)d_in[21];
    const float* W2    = (const float*)d_in[22];
    const float* b2    = (const float*)d_in[23];
    const float* Wkvp  = (const float*)d_in[24];
    const float* bkvp  = (const float*)d_in[25];
    const float* Wout  = (const float*)d_in[26];
    const float* bout  = (const float*)d_in[27];

    float* out   = (float*)d_out;
    float* out_s = out;                                   // (B,N,CS)
    float* out_g = out + (size_t)Bc*Nc*CSc;               // (B,N,N,G)

    tok_kernel<<<NTOK/8, 256>>>(s, ln_g, ln_b, Wq, bq, Wkv, bkv,
                                Wpq, bpq, Wpv, bpv, Wkvp, bkvp);
    vg_kernel<<<(NTOK*96 + 255)/256, 256>>>(rot, trans);
    qk_kernel<<<dim3(8, 12, 2), 256>>>();

    cudaFuncSetAttribute(pair_kernel, cudaFuncAttributeMaxDynamicSharedMemorySize,
                         PAIR_SMEM_BYTES);
    pair_kernel<<<NTOK, 256, PAIR_SMEM_BYTES>>>(rot, trans, mask, hwts, Wvl, gm, gs,
                                                Wg, bg, W1, b1, W2, b2, out_g);
    softmax_kernel<<<NTOK, 128>>>();
    av_kernel<<<dim3(8, 12, 2), 256>>>();
    final_kernel<<<NTOK/16, 256>>>(rot, trans, Wout, bout, out_s);
}

// round 11
// speedup vs baseline: 1.0125x; 1.0016x over previous
#include <cuda_runtime.h>
#include <math.h>

// ---------------------------------------------------------------------------
// Problem constants (fixed shapes)
// ---------------------------------------------------------------------------
#define Bc   2
#define Nc   512
#define CSc  384
#define Hc   12
#define Cc   16
#define Pc   8
#define PVc  8
#define Kc   16
#define Gc   64
#define NTOK (Bc*Nc)          // 1024
#define SCALEF 0.1f
#define INFF   100000.0f

// scratch (device globals; no allocation allowed)
__device__ float d_q   [NTOK*Hc*Cc];      // 1024*192
__device__ float d_k   [NTOK*Hc*Cc];
__device__ float d_v   [NTOK*Hc*Cc];
__device__ float d_qpts[NTOK*Pc*3];       // 1024*24
__device__ float d_vpts[NTOK*Pc*3];
__device__ float d_kvp [NTOK*Hc*PVc*3];   // 1024*288
__device__ float d_vg  [NTOK*Hc*PVc*3];
__device__ float d_apre[(size_t)Bc*Nc*Hc*Nc]; // (b,i,h,j) 6.29M floats
__device__ float d_o   [NTOK*Hc*Cc];      // attention feature out
__device__ float d_opt [NTOK*Hc*PVc*3];   // attention point out (global frame)

// ---------------------------------------------------------------------------
// Kernel 1: per-token projections (8 tokens per block, register blocking)
// ---------------------------------------------------------------------------
__global__ void tok_kernel(
    const float* __restrict__ s_in,
    const float* __restrict__ ln_g, const float* __restrict__ ln_b,
    const float* __restrict__ Wq,   const float* __restrict__ bq,
    const float* __restrict__ Wkv,  const float* __restrict__ bkv,
    const float* __restrict__ Wpq,  const float* __restrict__ bpq,
    const float* __restrict__ Wpv,  const float* __restrict__ bpv,
    const float* __restrict__ Wkvp, const float* __restrict__ bkvp)
{
    __shared__ float s_s [8][CSc];
    __shared__ float sn_s[8][CSc];
    int t = threadIdx.x, wid = t >> 5, lane = t & 31;
    int tok0 = blockIdx.x * 8;

    for (int x = t; x < 8*CSc; x += 256) ((float*)s_s)[x] = s_in[tok0*CSc + x];
    __syncthreads();

    {
        float ps = 0.f, pq = 0.f;
        for (int kk = lane; kk < CSc; kk += 32) { float v = s_s[wid][kk]; ps += v; pq += v*v; }
        #pragma unroll
        for (int o = 16; o; o >>= 1) {
            ps += __shfl_xor_sync(0xffffffffu, ps, o);
            pq += __shfl_xor_sync(0xffffffffu, pq, o);
        }
        float mean = ps * (1.f/CSc);
        float var  = pq * (1.f/CSc) - mean*mean;
        float inv  = rsqrtf(var + 1e-5f);
        for (int kk = lane; kk < CSc; kk += 32)
            sn_s[wid][kk] = (s_s[wid][kk] - mean) * inv * ln_g[kk] + ln_b[kk];
    }
    __syncthreads();

    for (int idx = t; idx < 912; idx += 256) {
        const float *W, *bias, *src; float* dst; int outdim, col, dstride;
        if (idx < 192)      { col = idx;     W = Wq;   bias = bq;   outdim = 192; src = (const float*)s_s;  dst = d_q;    dstride = 192; }
        else if (idx < 576) { col = idx-192; W = Wkv;  bias = bkv;  outdim = 384; src = (const float*)s_s;  dst = 0;      dstride = 0;   }
        else if (idx < 600) { col = idx-576; W = Wpq;  bias = bpq;  outdim = 24;  src = (const float*)sn_s; dst = d_qpts; dstride = 24;  }
        else if (idx < 624) { col = idx-600; W = Wpv;  bias = bpv;  outdim = 24;  src = (const float*)sn_s; dst = d_vpts; dstride = 24;  }
        else                { col = idx-624; W = Wkvp; bias = bkvp; outdim = 288; src = (const float*)s_s;  dst = d_kvp;  dstride = 288; }
        float acc[8];
        float bv = bias[col];
        #pragma unroll
        for (int tt = 0; tt < 8; tt++) acc[tt] = bv;
        for (int kk = 0; kk < CSc; kk++) {
            float w = W[kk*outdim + col];
            #pragma unroll
            for (int tt = 0; tt < 8; tt++) acc[tt] += src[tt*CSc + kk] * w;
        }
        if (dst) {
            #pragma unroll
            for (int tt = 0; tt < 8; tt++) dst[(tok0+tt)*dstride + col] = acc[tt];
        } else {
            int h = col >> 5, cc = col & 31;
            if (cc < 16) { for (int tt = 0; tt < 8; tt++) d_k[(tok0+tt)*192 + h*16 + cc]      = acc[tt]; }
            else         { for (int tt = 0; tt < 8; tt++) d_v[(tok0+tt)*192 + h*16 + cc - 16] = acc[tt]; }
        }
    }
}

// ---------------------------------------------------------------------------
// Kernel 2: global value points  vg = R_j @ kv_pts + trans_j*SCALE
// ---------------------------------------------------------------------------
__global__ void vg_kernel(const float* __restrict__ rot, const float* __restrict__ trans)
{
    int idx = blockIdx.x*256 + threadIdx.x;
    if (idx >= NTOK*96) return;
    int tok = idx / 96, pidx = idx % 96;
    float p0 = d_kvp[tok*288 + pidx*3 + 0];
    float p1 = d_kvp[tok*288 + pidx*3 + 1];
    float p2 = d_kvp[tok*288 + pidx*3 + 2];
    const float* R = rot + tok*9;
    #pragma unroll
    for (int x = 0; x < 3; x++)
        d_vg[tok*288 + pidx*3 + x] =
            R[x*3+0]*p0 + R[x*3+1]*p1 + R[x*3+2]*p2 + trans[tok*3+x]*SCALEF;
}

// ---------------------------------------------------------------------------
// Kernel 3: qk GEMM — pre-writes qk*0.125 into d_apre
//   block = (itile64, h, b); C[64i,512j] = Q[64i,16] @ K[512j,16]^T
// ---------------------------------------------------------------------------
__global__ void qk_kernel()
{
    __shared__ float Q_s[64][17];
    __shared__ float K_s[64][17];
    int t = threadIdx.x;
    int i0 = blockIdx.x * 64, h = blockIdx.y, b = blockIdx.z;
    int jg = t & 15, ig = t >> 4;          // 16x16 thread grid, 4x4 outputs each

    for (int idx = t; idx < 64*16; idx += 256) {
        int r = idx >> 4, c = idx & 15;
        Q_s[r][c] = d_q[(b*512 + i0 + r)*192 + h*16 + c];
    }
    for (int jt = 0; jt < 8; jt++) {
        int j0 = jt * 64;
        __syncthreads();   // protect K_s from previous iter readers
        for (int idx = t; idx < 64*16; idx += 256) {
            int r = idx >> 4, c = idx & 15;
            K_s[r][c] = d_k[(b*512 + j0 + r)*192 + h*16 + c];
        }
        __syncthreads();
        float acc[4][4];
        #pragma unroll
        for (int a = 0; a < 4; a++)
            #pragma unroll
            for (int c = 0; c < 4; c++) acc[a][c] = 0.f;
        #pragma unroll
        for (int kk = 0; kk < 16; kk++) {
            float qv[4], kv[4];
            #pragma unroll
            for (int u = 0; u < 4; u++) { qv[u] = Q_s[ig*4+u][kk]; kv[u] = K_s[jg*4+u][kk]; }
            #pragma unroll
            for (int a = 0; a < 4; a++)
                #pragma unroll
                for (int c = 0; c < 4; c++) acc[a][c] += qv[a]*kv[c];
        }
        #pragma unroll
        for (int a = 0; a < 4; a++) {
            float4 v = make_float4(acc[a][0]*0.125f, acc[a][1]*0.125f,
                                   acc[a][2]*0.125f, acc[a][3]*0.125f);
            *(float4*)&d_apre[(((size_t)(b*512 + i0 + ig*4 + a))*12 + h)*512 + j0 + jg*4] = v;
        }
    }
}

// ---------------------------------------------------------------------------
// Kernel 4: pair kernel — one block per (b,i), 8 tiles of 64 j's
//   Weights Wg/W1 from GLOBAL (L1-cached); qk prevalue read from d_apre
// ---------------------------------------------------------------------------
// smem carve (floats)
#define SO_W2    0                      // [64][12]
#define SO_GAUSS (SO_W2   + 768)        // [64][132]
#define SO_G     (SO_GAUSS+ 8448)       // [64][68]
#define SO_H1    (SO_G    + 4352)       // [64][65]
#define SO_VLOC  (SO_H1   + 4160)       // [64][8][3]
#define SO_RT    (SO_VLOC + 1536)       // [64][12]
#define SO_PD    (SO_RT   + 768)        // 64
#define SO_MJ    (SO_PD   + 64)         // 64
#define SO_BG    (SO_MJ   + 64)         // 64
#define SO_B1    (SO_BG   + 64)         // 64
#define SO_B2    (SO_B1   + 64)         // 16
#define SO_HW    (SO_B2   + 16)         // 16
#define SO_WVL   (SO_HW   + 16)         // 128
#define SO_MEAN  (SO_WVL  + 128)        // 16
#define SO_ISTD  (SO_MEAN + 16)         // 16
#define SO_QP    (SO_ISTD + 16)         // 24
#define SO_RI    (SO_QP   + 24)         // 12
#define SO_TI    (SO_RI   + 12)         // 4
#define SO_MI    (SO_TI   + 4)          // 4
#define PAIR_SMEM_FLOATS (SO_MI + 4)
#define PAIR_SMEM_BYTES  (PAIR_SMEM_FLOATS*4)

__global__ void __launch_bounds__(256, 2) pair_kernel(
    const float* __restrict__ rot, const float* __restrict__ trans,
    const float* __restrict__ mask, const float* __restrict__ head_weights,
    const float* __restrict__ Wvl, const float* __restrict__ gbf_means,
    const float* __restrict__ gbf_stds,
    const float* __restrict__ Wg, const float* __restrict__ bg,
    const float* __restrict__ W1, const float* __restrict__ b1,
    const float* __restrict__ W2, const float* __restrict__ b2,
    float* __restrict__ out_g)
{
    extern __shared__ float sm[];
    float* W2_s   = sm + SO_W2;
    float* gauss_s= sm + SO_GAUSS;  // [j][132]
    float* g_s    = sm + SO_G;      // [j][68]
    float* h1_s   = sm + SO_H1;     // [j][65]
    float* vloc_s = sm + SO_VLOC;   // [j][8][3]
    float* RT_s   = sm + SO_RT;     // [j][12]
    float* pd_s   = sm + SO_PD;
    float* mj_s   = sm + SO_MJ;
    float* bg_s   = sm + SO_BG;
    float* b1_s   = sm + SO_B1;
    float* b2_s   = sm + SO_B2;
    float* hw_s   = sm + SO_HW;
    float* Wvl_s  = sm + SO_WVL;
    float* mean_s = sm + SO_MEAN;
    float* istd_s = sm + SO_ISTD;
    float* qpts_s = sm + SO_QP;
    float* Ri_s   = sm + SO_RI;
    float* ti_s   = sm + SO_TI;
    float* mi_s   = sm + SO_MI;

    int t = threadIdx.x;
    int toki = blockIdx.x;
    int b = toki >> 9;

    for (int x = t; x < 768;  x += 256) W2_s[x] = W2[x];
    if (t < 64) { bg_s[t] = bg[t]; b1_s[t] = b1[t]; }
    if (t < 12) {
        b2_s[t] = b2[t];
        float x = head_weights[t];
        float sp = (x > 20.f) ? x : log1pf(expf(x));
        hw_s[t] = sp * 0.23570226f * -0.5f;   // sqrt(1/(AFS*4.5)) * -0.5
    }
    if (t < 128) Wvl_s[t] = Wvl[t];
    if (t < 16) { mean_s[t] = gbf_means[t]; istd_s[t] = 1.f / gbf_stds[t]; }
    if (t < 24) qpts_s[t] = d_qpts[toki*24 + t];
    if (t < 9)  Ri_s[t]   = rot[toki*9 + t];
    if (t < 3)  ti_s[t]   = trans[toki*3 + t];
    if (t == 0) mi_s[0]   = mask[toki];
    __syncthreads();

    int og = t & 15, jg = t >> 4;       // register-tile coords for P4/P5
    int o0 = og * 4, j0r = jg * 4;

    for (int jt = 0; jt < 8; jt++) {
        int j0 = jt * 64;
        // ---- P1: per-j relative frame, pair_dist, mask ----
        if (t < 64) {
            int tokj = b*512 + j0 + t;
            float Rj[9], tj[3];
            #pragma unroll
            for (int x = 0; x < 9; x++) Rj[x] = rot[tokj*9 + x];
            #pragma unroll
            for (int x = 0; x < 3; x++) tj[x] = trans[tokj*3 + x];
            #pragma unroll
            for (int x = 0; x < 3; x++)
                #pragma unroll
                for (int z = 0; z < 3; z++)
                    RT_s[t*12 + x*3 + z] =
                        Ri_s[0*3+x]*Rj[0*3+z] + Ri_s[1*3+x]*Rj[1*3+z] + Ri_s[2*3+x]*Rj[2*3+z];
            float dt0 = tj[0]-ti_s[0], dt1 = tj[1]-ti_s[1], dt2 = tj[2]-ti_s[2];
            #pragma unroll
            for (int x = 0; x < 3; x++)
                RT_s[t*12 + 9 + x] = Ri_s[0*3+x]*dt0 + Ri_s[1*3+x]*dt1 + Ri_s[2*3+x]*dt2;
            pd_s[t] = (dt0*dt0 + dt1*dt1 + dt2*dt2) * (SCALEF*SCALEF);
            mj_s[t] = mask[tokj];
        }
        __syncthreads();

        // ---- P2: v_loc = Rrel @ v_pts_j + t_rel  (512 items, 2/thread) ----
        #pragma unroll
        for (int pass = 0; pass < 2; pass++) {
            int idx = t + pass*256;
            int jl = idx >> 3, p = idx & 7;
            int tokj = b*512 + j0 + jl;
            float vx = d_vpts[tokj*24 + p*3 + 0];
            float vy = d_vpts[tokj*24 + p*3 + 1];
            float vz = d_vpts[tokj*24 + p*3 + 2];
            const float* RT = RT_s + jl*12;
            #pragma unroll
            for (int x = 0; x < 3; x++)
                vloc_s[(jl*8+p)*3 + x] = RT[x*3+0]*vx + RT[x*3+1]*vy + RT[x*3+2]*vz + RT[9+x];
        }
        __syncthreads();

        // ---- P3: vec / vlen / gauss  (512 items, 2/thread) ----
        #pragma unroll
        for (int pass = 0; pass < 2; pass++) {
            int idx = t + pass*256;
            int jl = idx >> 3, o = idx & 7;
            float vec[3];
            #pragma unroll
            for (int c = 0; c < 3; c++) {
                float a = vloc_s[(jl*8+o)*3 + c];
                #pragma unroll
                for (int p = 0; p < 8; p++) {
                    a += Wvl_s[o*16 + p]     * vloc_s[(jl*8+p)*3 + c];
                    a += Wvl_s[o*16 + 8 + p] * qpts_s[p*3 + c];
                }
                vec[c] = a;
            }
            float vlen = sqrtf(vec[0]*vec[0] + vec[1]*vec[1] + vec[2]*vec[2] + 1e-8f);
            float gv[16];
            #pragma unroll
            for (int k = 0; k < 16; k++) {
                float zz = (vlen - mean_s[k]) * istd_s[k];
                gv[k] = __expf(-0.5f*zz*zz);
            }
            float* gp = gauss_s + jl*132 + o*16;
            #pragma unroll
            for (int k4 = 0; k4 < 4; k4++)
                *(float4*)&gp[k4*4] = make_float4(gv[k4*4], gv[k4*4+1], gv[k4*4+2], gv[k4*4+3]);
        }
        __syncthreads();

        // ---- P4: g = gauss @ Wg + bg  (4j x 4o per thread; Wg from L1) ----
        {
            float acc[4][4];
            #pragma unroll
            for (int jj = 0; jj < 4; jj++)
                #pragma unroll
                for (int u = 0; u < 4; u++) acc[jj][u] = bg_s[o0+u];
            const float* gp = gauss_s + j0r*132;
            #pragma unroll 4
            for (int kk = 0; kk < 128; kk++) {
                float a0 = gp[kk], a1 = gp[132+kk], a2 = gp[264+kk], a3 = gp[396+kk];
                float4 w = *(const float4*)&Wg[kk*64 + o0];
                acc[0][0] += a0*w.x; acc[0][1] += a0*w.y; acc[0][2] += a0*w.z; acc[0][3] += a0*w.w;
                acc[1][0] += a1*w.x; acc[1][1] += a1*w.y; acc[1][2] += a1*w.z; acc[1][3] += a1*w.w;
                acc[2][0] += a2*w.x; acc[2][1] += a2*w.y; acc[2][2] += a2*w.z; acc[2][3] += a2*w.w;
                acc[3][0] += a3*w.x; acc[3][1] += a3*w.y; acc[3][2] += a3*w.z; acc[3][3] += a3*w.w;
            }
            #pragma unroll
            for (int jj = 0; jj < 4; jj++) {
                float4 v = make_float4(acc[jj][0], acc[jj][1], acc[jj][2], acc[jj][3]);
                *(float4*)&g_s[(j0r+jj)*68 + o0] = v;
                *(float4*)&out_g[((size_t)toki*512 + (j0 + j0r + jj))*64 + o0] = v;
            }
        }
        __syncthreads();

        // ---- P5: h1 = relu(g @ W1 + b1)  (4j x 4o; W1 from L1) ----
        {
            float acc[4][4];
            #pragma unroll
            for (int jj = 0; jj < 4; jj++)
                #pragma unroll
                for (int u = 0; u < 4; u++) acc[jj][u] = b1_s[o0+u];
            const float* gp = g_s + j0r*68;
            #pragma unroll 4
            for (int kk = 0; kk < 64; kk++) {
                float a0 = gp[kk], a1 = gp[68+kk], a2 = gp[136+kk], a3 = gp[204+kk];
                float4 w = *(const float4*)&W1[kk*64 + o0];
                acc[0][0] += a0*w.x; acc[0][1] += a0*w.y; acc[0][2] += a0*w.z; acc[0][3] += a0*w.w;
                acc[1][0] += a1*w.x; acc[1][1] += a1*w.y; acc[1][2] += a1*w.z; acc[1][3] += a1*w.w;
                acc[2][0] += a2*w.x; acc[2][1] += a2*w.y; acc[2][2] += a2*w.z; acc[2][3] += a2*w.w;
                acc[3][0] += a3*w.x; acc[3][1] += a3*w.y; acc[3][2] += a3*w.z; acc[3][3] += a3*w.w;
            }
            #pragma unroll
            for (int jj = 0; jj < 4; jj++) {
                float* hp = &h1_s[(j0r+jj)*65 + o0];
                hp[0] = fmaxf(acc[jj][0], 0.f);
                hp[1] = fmaxf(acc[jj][1], 0.f);
                hp[2] = fmaxf(acc[jj][2], 0.f);
                hp[3] = fmaxf(acc[jj][3], 0.f);
            }
        }
        __syncthreads();

        // ---- P6: vfn = h1 @ W2 + b2 ; combine with pre-written qk ----
        #pragma unroll
        for (int pass = 0; pass < 3; pass++) {
            int idx = t + pass*256;
            int jl = idx & 63, h = idx >> 6;
            float a0 = 0.f, a1 = 0.f, a2 = 0.f, a3 = 0.f;
            const float* hh = h1_s + jl*65;
            const float* w2 = W2_s + h;
            #pragma unroll 4
            for (int kk = 0; kk < 64; kk += 4) {
                a0 += hh[kk]   * w2[kk*12];
                a1 += hh[kk+1] * w2[(kk+1)*12];
                a2 += hh[kk+2] * w2[(kk+2)*12];
                a3 += hh[kk+3] * w2[(kk+3)*12];
            }
            float acc = b2_s[h] + (a0+a1) + (a2+a3);
            int j = j0 + jl;
            size_t aidx = ((size_t)toki*12 + h)*512 + j;
            float pre = d_apre[aidx];   // qk*0.125 from qk_kernel (coalesced)
            float logit = pre + acc*0.5f + pd_s[jl]*hw_s[h]
                        + INFF*(mi_s[0]*mj_s[jl] - 1.0f);
            d_apre[aidx] = logit;
        }
        __syncthreads();
    }
}

// ---------------------------------------------------------------------------
// Kernel 5: softmax over j (in-place on d_apre), register-cached rows
// ---------------------------------------------------------------------------
__global__ void softmax_kernel()
{
    int toki = blockIdx.x;
    int t = threadIdx.x, wid = t >> 5, lane = t & 31;
    for (int h = wid; h < 12; h += 4) {
        float* row = d_apre + ((size_t)toki*12 + h)*512;
        float r[16];
        float m = -1e30f;
        #pragma unroll
        for (int kk = 0; kk < 16; kk++) { r[kk] = row[lane + kk*32]; m = fmaxf(m, r[kk]); }
        #pragma unroll
        for (int o = 16; o; o >>= 1) m = fmaxf(m, __shfl_xor_sync(0xffffffffu, m, o));
        float sum = 0.f;
        #pragma unroll
        for (int kk = 0; kk < 16; kk++) { r[kk] = __expf(r[kk] - m); sum += r[kk]; }
        #pragma unroll
        for (int o = 16; o; o >>= 1) sum += __shfl_xor_sync(0xffffffffu, sum, o);
        float inv = 1.f / sum;
        #pragma unroll
        for (int kk = 0; kk < 16; kk++) row[lane + kk*32] = r[kk] * inv;
    }
}

// ---------------------------------------------------------------------------
// Kernel 6: AV GEMM — per (b,h,itile64): C[64i][40s] = A[64i,512j] @ Vt[512j,40s]
// ---------------------------------------------------------------------------
__global__ void av_kernel()
{
    __shared__ float A_s[64][65];
    __shared__ float Vt_s[64][40];
    int t = threadIdx.x;
    int itile = blockIdx.x, h = blockIdx.y, b = blockIdx.z;
    int i0 = itile * 64;
    int il = t & 63, sg = t >> 6;

    float acc[10];
    #pragma unroll
    for (int u = 0; u < 10; u++) acc[u] = 0.f;

    for (int jtt = 0; jtt < 8; jtt++) {
        int j0 = jtt * 64;
        for (int idx = t; idx < 4096; idx += 256) {
            int rr = idx >> 6, cc = idx & 63;
            A_s[rr][cc] = d_apre[(((size_t)(b*512 + i0 + rr))*12 + h)*512 + j0 + cc];
        }
        for (int idx = t; idx < 2560; idx += 256) {
            int jj = idx / 40, ss = idx % 40;
            int tok = b*512 + j0 + jj;
            Vt_s[jj][ss] = (ss < 16) ? d_v[tok*192 + h*16 + ss]
                                     : d_vg[tok*288 + h*24 + (ss-16)];
        }
        __syncthreads();
        #pragma unroll 4
        for (int jj = 0; jj < 64; jj++) {
            float a = A_s[il][jj];
            #pragma unroll
            for (int u = 0; u < 10; u++) acc[u] += a * Vt_s[jj][sg*10 + u];
        }
        __syncthreads();
    }
    int tok = b*512 + i0 + il;
    #pragma unroll
    for (int u = 0; u < 10; u++) {
        int ss = sg*10 + u;
        if (ss < 16) d_o  [tok*192 + h*16 + ss]      = acc[u];
        else         d_opt[tok*288 + h*24 + (ss-16)] = acc[u];
    }
}

// ---------------------------------------------------------------------------
// Kernel 7: local transform + dists + final GEMM (16 tokens per block)
// ---------------------------------------------------------------------------
__global__ void final_kernel(
    const float* __restrict__ rot, const float* __restrict__ trans,
    const float* __restrict__ Wout, const float* __restrict__ bout,
    float* __restrict__ out_s)
{
    __shared__ float feats[16][577];
    int t = threadIdx.x;
    int tok0 = blockIdx.x * 16;

    for (int idx = t; idx < 16*192; idx += 256) {
        int tt = idx / 192, cc = idx % 192;
        feats[tt][cc] = d_o[(tok0+tt)*192 + cc];
    }
    for (int idx = t; idx < 16*96; idx += 256) {
        int tt = idx / 96, pp = idx % 96;
        int tok = tok0 + tt;
        float px = d_opt[tok*288 + pp*3 + 0] - trans[tok*3+0]*SCALEF;
        float py = d_opt[tok*288 + pp*3 + 1] - trans[tok*3+1]*SCALEF;
        float pz = d_opt[tok*288 + pp*3 + 2] - trans[tok*3+2]*SCALEF;
        const float* R = rot + tok*9;
        float lx = R[0]*px + R[3]*py + R[6]*pz;
        float ly = R[1]*px + R[4]*py + R[7]*pz;
        float lz = R[2]*px + R[5]*py + R[8]*pz;
        float d  = sqrtf(lx*lx + ly*ly + lz*lz + 1e-8f);
        feats[tt][192 + pp] = lx;
        feats[tt][288 + pp] = ly;
        feats[tt][384 + pp] = lz;
        feats[tt][480 + pp] = d;
    }
    __syncthreads();

    for (int o = t; o < 384; o += 256) {
        float acc[16];
        float bv = bout[o];
        #pragma unroll
        for (int tt = 0; tt < 16; tt++) acc[tt] = bv;
        for (int kk = 0; kk < 576; kk++) {
            float w = Wout[kk*384 + o];
            #pragma unroll
            for (int tt = 0; tt < 16; tt++) acc[tt] += feats[tt][kk] * w;
        }
        #pragma unroll
        for (int tt = 0; tt < 16; tt++) out_s[(size_t)(tok0+tt)*384 + o] = acc[tt];
    }
}

// ---------------------------------------------------------------------------
// launch
// ---------------------------------------------------------------------------
extern "C" void kernel_launch(void* const* d_in, const int* in_sizes, int n_in,
                              void* d_out, int out_size)
{
    const float* s     = (const float*)d_in[0];
    const float* rot   = (const float*)d_in[1];
    const float* trans = (const float*)d_in[2];
    const float* mask  = (const float*)d_in[3];
    const float* Wq    = (const float*)d_in[4];
    const float* bq    = (const float*)d_in[5];
    const float* Wkv   = (const float*)d_in[6];
    const float* bkv   = (const float*)d_in[7];
    const float* hwts  = (const float*)d_in[8];
    const float* ln_g  = (const float*)d_in[9];
    const float* ln_b  = (const float*)d_in[10];
    const float* Wpq   = (const float*)d_in[11];
    const float* bpq   = (const float*)d_in[12];
    const float* Wpv   = (const float*)d_in[13];
    const float* bpv   = (const float*)d_in[14];
    const float* Wvl   = (const float*)d_in[15];
    const float* gm    = (const float*)d_in[16];
    const float* gs    = (const float*)d_in[17];
    const float* Wg    = (const float*)d_in[18];
    const float* bg    = (const float*)d_in[19];
    const float* W1    = (const float*)d_in[20];
    const float* b1    = (const float*)d_in[21];
    const float* W2    = (const float*)d_in[22];
    const float* b2    = (const float*)d_in[23];
    const float* Wkvp  = (const float*)d_in[24];
    const float* bkvp  = (const float*)d_in[25];
    const float* Wout  = (const float*)d_in[26];
    const float* bout  = (const float*)d_in[27];

    float* out   = (float*)d_out;
    float* out_s = out;                                   // (B,N,CS)
    float* out_g = out + (size_t)Bc*Nc*CSc;               // (B,N,N,G)

    tok_kernel<<<NTOK/8, 256>>>(s, ln_g, ln_b, Wq, bq, Wkv, bkv,
                                Wpq, bpq, Wpv, bpv, Wkvp, bkvp);
    vg_kernel<<<(NTOK*96 + 255)/256, 256>>>(rot, trans);
    qk_kernel<<<dim3(8, 12, 2), 256>>>();

    cudaFuncSetAttribute(pair_kernel, cudaFuncAttributeMaxDynamicSharedMemorySize,
                         PAIR_SMEM_BYTES);
    pair_kernel<<<NTOK, 256, PAIR_SMEM_BYTES>>>(rot, trans, mask, hwts, Wvl, gm, gs,
                                                Wg, bg, W1, b1, W2, b2, out_g);
    softmax_kernel<<<NTOK, 128>>>();
    av_kernel<<<dim3(8, 12, 2), 256>>>();
    final_kernel<<<NTOK/16, 256>>>(rot, trans, Wout, bout, out_s);
}

// round 12
// speedup vs baseline: 1.0141x; 1.0016x over previous
#include <cuda_runtime.h>
#include <math.h>

// ---------------------------------------------------------------------------
// Problem constants (fixed shapes)
// ---------------------------------------------------------------------------
#define Bc   2
#define Nc   512
#define CSc  384
#define Hc   12
#define Cc   16
#define Pc   8
#define PVc  8
#define Kc   16
#define Gc   64
#define NTOK (Bc*Nc)          // 1024
#define SCALEF 0.1f
#define INFF   100000.0f

// scratch (device globals; no allocation allowed)
__device__ float d_q   [NTOK*Hc*Cc];      // 1024*192
__device__ float d_k   [NTOK*Hc*Cc];
__device__ float d_v   [NTOK*Hc*Cc];
__device__ float d_qpts[NTOK*Pc*3];       // 1024*24
__device__ float d_vpts[NTOK*Pc*3];
__device__ float d_kvp [NTOK*Hc*PVc*3];   // 1024*288
__device__ float d_vg  [NTOK*Hc*PVc*3];
__device__ float d_apre[(size_t)Bc*Nc*Hc*Nc]; // (b,i,h,j) 6.29M floats
__device__ float d_o   [NTOK*Hc*Cc];      // attention feature out
__device__ float d_opt [NTOK*Hc*PVc*3];   // attention point out (global frame)

// ---------------------------------------------------------------------------
// Kernel 1: per-token projections (8 tokens per block, register blocking)
// ---------------------------------------------------------------------------
__global__ void tok_kernel(
    const float* __restrict__ s_in,
    const float* __restrict__ ln_g, const float* __restrict__ ln_b,
    const float* __restrict__ Wq,   const float* __restrict__ bq,
    const float* __restrict__ Wkv,  const float* __restrict__ bkv,
    const float* __restrict__ Wpq,  const float* __restrict__ bpq,
    const float* __restrict__ Wpv,  const float* __restrict__ bpv,
    const float* __restrict__ Wkvp, const float* __restrict__ bkvp)
{
    __shared__ float s_s [8][CSc];
    __shared__ float sn_s[8][CSc];
    int t = threadIdx.x, wid = t >> 5, lane = t & 31;
    int tok0 = blockIdx.x * 8;

    for (int x = t; x < 8*CSc; x += 256) ((float*)s_s)[x] = s_in[tok0*CSc + x];
    __syncthreads();

    {
        float ps = 0.f, pq = 0.f;
        for (int kk = lane; kk < CSc; kk += 32) { float v = s_s[wid][kk]; ps += v; pq += v*v; }
        #pragma unroll
        for (int o = 16; o; o >>= 1) {
            ps += __shfl_xor_sync(0xffffffffu, ps, o);
            pq += __shfl_xor_sync(0xffffffffu, pq, o);
        }
        float mean = ps * (1.f/CSc);
        float var  = pq * (1.f/CSc) - mean*mean;
        float inv  = rsqrtf(var + 1e-5f);
        for (int kk = lane; kk < CSc; kk += 32)
            sn_s[wid][kk] = (s_s[wid][kk] - mean) * inv * ln_g[kk] + ln_b[kk];
    }
    __syncthreads();

    for (int idx = t; idx < 912; idx += 256) {
        const float *W, *bias, *src; float* dst; int outdim, col, dstride;
        if (idx < 192)      { col = idx;     W = Wq;   bias = bq;   outdim = 192; src = (const float*)s_s;  dst = d_q;    dstride = 192; }
        else if (idx < 576) { col = idx-192; W = Wkv;  bias = bkv;  outdim = 384; src = (const float*)s_s;  dst = 0;      dstride = 0;   }
        else if (idx < 600) { col = idx-576; W = Wpq;  bias = bpq;  outdim = 24;  src = (const float*)sn_s; dst = d_qpts; dstride = 24;  }
        else if (idx < 624) { col = idx-600; W = Wpv;  bias = bpv;  outdim = 24;  src = (const float*)sn_s; dst = d_vpts; dstride = 24;  }
        else                { col = idx-624; W = Wkvp; bias = bkvp; outdim = 288; src = (const float*)s_s;  dst = d_kvp;  dstride = 288; }
        float acc[8];
        float bv = bias[col];
        #pragma unroll
        for (int tt = 0; tt < 8; tt++) acc[tt] = bv;
        for (int kk = 0; kk < CSc; kk++) {
            float w = W[kk*outdim + col];
            #pragma unroll
            for (int tt = 0; tt < 8; tt++) acc[tt] += src[tt*CSc + kk] * w;
        }
        if (dst) {
            #pragma unroll
            for (int tt = 0; tt < 8; tt++) dst[(tok0+tt)*dstride + col] = acc[tt];
        } else {
            int h = col >> 5, cc = col & 31;
            if (cc < 16) { for (int tt = 0; tt < 8; tt++) d_k[(tok0+tt)*192 + h*16 + cc]      = acc[tt]; }
            else         { for (int tt = 0; tt < 8; tt++) d_v[(tok0+tt)*192 + h*16 + cc - 16] = acc[tt]; }
        }
    }
}

// ---------------------------------------------------------------------------
// Kernel 2: global value points  vg = R_j @ kv_pts + trans_j*SCALE
// ---------------------------------------------------------------------------
__global__ void vg_kernel(const float* __restrict__ rot, const float* __restrict__ trans)
{
    int idx = blockIdx.x*256 + threadIdx.x;
    if (idx >= NTOK*96) return;
    int tok = idx / 96, pidx = idx % 96;
    float p0 = d_kvp[tok*288 + pidx*3 + 0];
    float p1 = d_kvp[tok*288 + pidx*3 + 1];
    float p2 = d_kvp[tok*288 + pidx*3 + 2];
    const float* R = rot + tok*9;
    #pragma unroll
    for (int x = 0; x < 3; x++)
        d_vg[tok*288 + pidx*3 + x] =
            R[x*3+0]*p0 + R[x*3+1]*p1 + R[x*3+2]*p2 + trans[tok*3+x]*SCALEF;
}

// ---------------------------------------------------------------------------
// Kernel 3: qk GEMM — pre-writes qk*0.125 into d_apre
//   block = (itile64, h, b); C[64i,512j] = Q[64i,16] @ K[512j,16]^T
// ---------------------------------------------------------------------------
__global__ void qk_kernel()
{
    __shared__ float Q_s[64][17];
    __shared__ float K_s[64][17];
    int t = threadIdx.x;
    int i0 = blockIdx.x * 64, h = blockIdx.y, b = blockIdx.z;
    int jg = t & 15, ig = t >> 4;          // 16x16 thread grid, 4x4 outputs each

    for (int idx = t; idx < 64*16; idx += 256) {
        int r = idx >> 4, c = idx & 15;
        Q_s[r][c] = d_q[(b*512 + i0 + r)*192 + h*16 + c];
    }
    for (int jt = 0; jt < 8; jt++) {
        int j0 = jt * 64;
        __syncthreads();   // protect K_s from previous iter readers
        for (int idx = t; idx < 64*16; idx += 256) {
            int r = idx >> 4, c = idx & 15;
            K_s[r][c] = d_k[(b*512 + j0 + r)*192 + h*16 + c];
        }
        __syncthreads();
        float acc[4][4];
        #pragma unroll
        for (int a = 0; a < 4; a++)
            #pragma unroll
            for (int c = 0; c < 4; c++) acc[a][c] = 0.f;
        #pragma unroll
        for (int kk = 0; kk < 16; kk++) {
            float qv[4], kv[4];
            #pragma unroll
            for (int u = 0; u < 4; u++) { qv[u] = Q_s[ig*4+u][kk]; kv[u] = K_s[jg*4+u][kk]; }
            #pragma unroll
            for (int a = 0; a < 4; a++)
                #pragma unroll
                for (int c = 0; c < 4; c++) acc[a][c] += qv[a]*kv[c];
        }
        #pragma unroll
        for (int a = 0; a < 4; a++) {
            float4 v = make_float4(acc[a][0]*0.125f, acc[a][1]*0.125f,
                                   acc[a][2]*0.125f, acc[a][3]*0.125f);
            *(float4*)&d_apre[(((size_t)(b*512 + i0 + ig*4 + a))*12 + h)*512 + j0 + jg*4] = v;
        }
    }
}

// ---------------------------------------------------------------------------
// Kernel 4: pair kernel — one block per (b,i), 8 tiles of 64 j's
//   Weights Wg/W1 from GLOBAL (L1-cached); qk prevalue read from d_apre
// ---------------------------------------------------------------------------
// smem carve (floats)
#define SO_W2    0                      // [64][12]
#define SO_GAUSS (SO_W2   + 768)        // [64][132]
#define SO_G     (SO_GAUSS+ 8448)       // [64][68]
#define SO_H1    (SO_G    + 4352)       // [64][65]
#define SO_VLOC  (SO_H1   + 4160)       // [64][8][3]
#define SO_RT    (SO_VLOC + 1536)       // [64][12]
#define SO_PD    (SO_RT   + 768)        // 64
#define SO_MJ    (SO_PD   + 64)         // 64
#define SO_BG    (SO_MJ   + 64)         // 64
#define SO_B1    (SO_BG   + 64)         // 64
#define SO_B2    (SO_B1   + 64)         // 16
#define SO_HW    (SO_B2   + 16)         // 16
#define SO_WVL   (SO_HW   + 16)         // 128
#define SO_MEAN  (SO_WVL  + 128)        // 16
#define SO_ISTD  (SO_MEAN + 16)         // 16
#define SO_QP    (SO_ISTD + 16)         // 24
#define SO_RI    (SO_QP   + 24)         // 12
#define SO_TI    (SO_RI   + 12)         // 4
#define SO_MI    (SO_TI   + 4)          // 4
#define PAIR_SMEM_FLOATS (SO_MI + 4)
#define PAIR_SMEM_BYTES  (PAIR_SMEM_FLOATS*4)

__global__ void __launch_bounds__(256, 2) pair_kernel(
    const float* __restrict__ rot, const float* __restrict__ trans,
    const float* __restrict__ mask, const float* __restrict__ head_weights,
    const float* __restrict__ Wvl, const float* __restrict__ gbf_means,
    const float* __restrict__ gbf_stds,
    const float* __restrict__ Wg, const float* __restrict__ bg,
    const float* __restrict__ W1, const float* __restrict__ b1,
    const float* __restrict__ W2, const float* __restrict__ b2,
    float* __restrict__ out_g)
{
    extern __shared__ float sm[];
    float* W2_s   = sm + SO_W2;
    float* gauss_s= sm + SO_GAUSS;  // [j][132]
    float* g_s    = sm + SO_G;      // [j][68]
    float* h1_s   = sm + SO_H1;     // [j][65]
    float* vloc_s = sm + SO_VLOC;   // [j][8][3]
    float* RT_s   = sm + SO_RT;     // [j][12]
    float* pd_s   = sm + SO_PD;
    float* mj_s   = sm + SO_MJ;
    float* bg_s   = sm + SO_BG;
    float* b1_s   = sm + SO_B1;
    float* b2_s   = sm + SO_B2;
    float* hw_s   = sm + SO_HW;
    float* Wvl_s  = sm + SO_WVL;
    float* mean_s = sm + SO_MEAN;
    float* istd_s = sm + SO_ISTD;
    float* qpts_s = sm + SO_QP;
    float* Ri_s   = sm + SO_RI;
    float* ti_s   = sm + SO_TI;
    float* mi_s   = sm + SO_MI;

    int t = threadIdx.x;
    int toki = blockIdx.x;
    int b = toki >> 9;

    for (int x = t; x < 768;  x += 256) W2_s[x] = W2[x];
    if (t < 64) { bg_s[t] = bg[t]; b1_s[t] = b1[t]; }
    if (t < 12) {
        b2_s[t] = b2[t];
        float x = head_weights[t];
        float sp = (x > 20.f) ? x : log1pf(expf(x));
        hw_s[t] = sp * 0.23570226f * -0.5f;   // sqrt(1/(AFS*4.5)) * -0.5
    }
    if (t < 128) Wvl_s[t] = Wvl[t];
    if (t < 16) { mean_s[t] = gbf_means[t]; istd_s[t] = 1.f / gbf_stds[t]; }
    if (t < 24) qpts_s[t] = d_qpts[toki*24 + t];
    if (t < 9)  Ri_s[t]   = rot[toki*9 + t];
    if (t < 3)  ti_s[t]   = trans[toki*3 + t];
    if (t == 0) mi_s[0]   = mask[toki];
    __syncthreads();

    int og = t & 15, jg = t >> 4;       // register-tile coords for P4/P5
    int o0 = og * 4, j0r = jg * 4;

    for (int jt = 0; jt < 8; jt++) {
        int j0 = jt * 64;
        // ---- P1: per-j relative frame, pair_dist, mask ----
        if (t < 64) {
            int tokj = b*512 + j0 + t;
            float Rj[9], tj[3];
            #pragma unroll
            for (int x = 0; x < 9; x++) Rj[x] = rot[tokj*9 + x];
            #pragma unroll
            for (int x = 0; x < 3; x++) tj[x] = trans[tokj*3 + x];
            #pragma unroll
            for (int x = 0; x < 3; x++)
                #pragma unroll
                for (int z = 0; z < 3; z++)
                    RT_s[t*12 + x*3 + z] =
                        Ri_s[0*3+x]*Rj[0*3+z] + Ri_s[1*3+x]*Rj[1*3+z] + Ri_s[2*3+x]*Rj[2*3+z];
            float dt0 = tj[0]-ti_s[0], dt1 = tj[1]-ti_s[1], dt2 = tj[2]-ti_s[2];
            #pragma unroll
            for (int x = 0; x < 3; x++)
                RT_s[t*12 + 9 + x] = Ri_s[0*3+x]*dt0 + Ri_s[1*3+x]*dt1 + Ri_s[2*3+x]*dt2;
            pd_s[t] = (dt0*dt0 + dt1*dt1 + dt2*dt2) * (SCALEF*SCALEF);
            mj_s[t] = mask[tokj];
        }
        __syncthreads();

        // ---- P2: v_loc = Rrel @ v_pts_j + t_rel  (512 items, 2/thread) ----
        #pragma unroll
        for (int pass = 0; pass < 2; pass++) {
            int idx = t + pass*256;
            int jl = idx >> 3, p = idx & 7;
            int tokj = b*512 + j0 + jl;
            float vx = d_vpts[tokj*24 + p*3 + 0];
            float vy = d_vpts[tokj*24 + p*3 + 1];
            float vz = d_vpts[tokj*24 + p*3 + 2];
            const float* RT = RT_s + jl*12;
            #pragma unroll
            for (int x = 0; x < 3; x++)
                vloc_s[(jl*8+p)*3 + x] = RT[x*3+0]*vx + RT[x*3+1]*vy + RT[x*3+2]*vz + RT[9+x];
        }
        __syncthreads();

        // ---- P3: vec / vlen / gauss  (512 items, 2/thread) ----
        #pragma unroll
        for (int pass = 0; pass < 2; pass++) {
            int idx = t + pass*256;
            int jl = idx >> 3, o = idx & 7;
            float vec[3];
            #pragma unroll
            for (int c = 0; c < 3; c++) {
                float a = vloc_s[(jl*8+o)*3 + c];
                #pragma unroll
                for (int p = 0; p < 8; p++) {
                    a += Wvl_s[o*16 + p]     * vloc_s[(jl*8+p)*3 + c];
                    a += Wvl_s[o*16 + 8 + p] * qpts_s[p*3 + c];
                }
                vec[c] = a;
            }
            float vlen = sqrtf(vec[0]*vec[0] + vec[1]*vec[1] + vec[2]*vec[2] + 1e-8f);
            float gv[16];
            #pragma unroll
            for (int k = 0; k < 16; k++) {
                float zz = (vlen - mean_s[k]) * istd_s[k];
                gv[k] = __expf(-0.5f*zz*zz);
            }
            float* gp = gauss_s + jl*132 + o*16;
            #pragma unroll
            for (int k4 = 0; k4 < 4; k4++)
                *(float4*)&gp[k4*4] = make_float4(gv[k4*4], gv[k4*4+1], gv[k4*4+2], gv[k4*4+3]);
        }
        __syncthreads();

        // ---- P4: g = gauss @ Wg + bg  (4j x 4o per thread; Wg from L1) ----
        {
            float acc[4][4];
            #pragma unroll
            for (int jj = 0; jj < 4; jj++)
                #pragma unroll
                for (int u = 0; u < 4; u++) acc[jj][u] = bg_s[o0+u];
            const float* gp = gauss_s + j0r*132;
            #pragma unroll 4
            for (int kk = 0; kk < 128; kk++) {
                float a0 = gp[kk], a1 = gp[132+kk], a2 = gp[264+kk], a3 = gp[396+kk];
                float4 w = *(const float4*)&Wg[kk*64 + o0];
                acc[0][0] += a0*w.x; acc[0][1] += a0*w.y; acc[0][2] += a0*w.z; acc[0][3] += a0*w.w;
                acc[1][0] += a1*w.x; acc[1][1] += a1*w.y; acc[1][2] += a1*w.z; acc[1][3] += a1*w.w;
                acc[2][0] += a2*w.x; acc[2][1] += a2*w.y; acc[2][2] += a2*w.z; acc[2][3] += a2*w.w;
                acc[3][0] += a3*w.x; acc[3][1] += a3*w.y; acc[3][2] += a3*w.z; acc[3][3] += a3*w.w;
            }
            #pragma unroll
            for (int jj = 0; jj < 4; jj++) {
                float4 v = make_float4(acc[jj][0], acc[jj][1], acc[jj][2], acc[jj][3]);
                *(float4*)&g_s[(j0r+jj)*68 + o0] = v;
                *(float4*)&out_g[((size_t)toki*512 + (j0 + j0r + jj))*64 + o0] = v;
            }
        }
        __syncthreads();

        // ---- P5: h1 = relu(g @ W1 + b1)  (4j x 4o; W1 from L1) ----
        {
            float acc[4][4];
            #pragma unroll
            for (int jj = 0; jj < 4; jj++)
                #pragma unroll
                for (int u = 0; u < 4; u++) acc[jj][u] = b1_s[o0+u];
            const float* gp = g_s + j0r*68;
            #pragma unroll 4
            for (int kk = 0; kk < 64; kk++) {
                float a0 = gp[kk], a1 = gp[68+kk], a2 = gp[136+kk], a3 = gp[204+kk];
                float4 w = *(const float4*)&W1[kk*64 + o0];
                acc[0][0] += a0*w.x; acc[0][1] += a0*w.y; acc[0][2] += a0*w.z; acc[0][3] += a0*w.w;
                acc[1][0] += a1*w.x; acc[1][1] += a1*w.y; acc[1][2] += a1*w.z; acc[1][3] += a1*w.w;
                acc[2][0] += a2*w.x; acc[2][1] += a2*w.y; acc[2][2] += a2*w.z; acc[2][3] += a2*w.w;
                acc[3][0] += a3*w.x; acc[3][1] += a3*w.y; acc[3][2] += a3*w.z; acc[3][3] += a3*w.w;
            }
            #pragma unroll
            for (int jj = 0; jj < 4; jj++) {
                float* hp = &h1_s[(j0r+jj)*65 + o0];
                hp[0] = fmaxf(acc[jj][0], 0.f);
                hp[1] = fmaxf(acc[jj][1], 0.f);
                hp[2] = fmaxf(acc[jj][2], 0.f);
                hp[3] = fmaxf(acc[jj][3], 0.f);
            }
        }
        __syncthreads();

        // ---- P6: vfn = h1 @ W2 + b2 ; combine with pre-written qk ----
        #pragma unroll
        for (int pass = 0; pass < 3; pass++) {
            int idx = t + pass*256;
            int jl = idx & 63, h = idx >> 6;
            float a0 = 0.f, a1 = 0.f, a2 = 0.f, a3 = 0.f;
            const float* hh = h1_s + jl*65;
            const float* w2 = W2_s + h;
            #pragma unroll 4
            for (int kk = 0; kk < 64; kk += 4) {
                a0 += hh[kk]   * w2[kk*12];
                a1 += hh[kk+1] * w2[(kk+1)*12];
                a2 += hh[kk+2] * w2[(kk+2)*12];
                a3 += hh[kk+3] * w2[(kk+3)*12];
            }
            float acc = b2_s[h] + (a0+a1) + (a2+a3);
            int j = j0 + jl;
            size_t aidx = ((size_t)toki*12 + h)*512 + j;
            float pre = d_apre[aidx];   // qk*0.125 from qk_kernel (coalesced)
            float logit = pre + acc*0.5f + pd_s[jl]*hw_s[h]
                        + INFF*(mi_s[0]*mj_s[jl] - 1.0f);
            d_apre[aidx] = logit;
        }
        __syncthreads();
    }
}

// ---------------------------------------------------------------------------
// Kernel 5: softmax over j (in-place on d_apre), register-cached rows
// ---------------------------------------------------------------------------
__global__ void softmax_kernel()
{
    int toki = blockIdx.x;
    int t = threadIdx.x, wid = t >> 5, lane = t & 31;
    for (int h = wid; h < 12; h += 4) {
        float* row = d_apre + ((size_t)toki*12 + h)*512;
        float r[16];
        float m = -1e30f;
        #pragma unroll
        for (int kk = 0; kk < 16; kk++) { r[kk] = row[lane + kk*32]; m = fmaxf(m, r[kk]); }
        #pragma unroll
        for (int o = 16; o; o >>= 1) m = fmaxf(m, __shfl_xor_sync(0xffffffffu, m, o));
        float sum = 0.f;
        #pragma unroll
        for (int kk = 0; kk < 16; kk++) { r[kk] = __expf(r[kk] - m); sum += r[kk]; }
        #pragma unroll
        for (int o = 16; o; o >>= 1) sum += __shfl_xor_sync(0xffffffffu, sum, o);
        float inv = 1.f / sum;
        #pragma unroll
        for (int kk = 0; kk < 16; kk++) row[lane + kk*32] = r[kk] * inv;
    }
}

// ---------------------------------------------------------------------------
// Kernel 6: AV GEMM — per (b,h,itile64): C[64i][40s] = A[64i,512j] @ Vt[512j,40s]
// ---------------------------------------------------------------------------
__global__ void av_kernel()
{
    __shared__ float A_s[64][65];
    __shared__ float Vt_s[64][40];
    int t = threadIdx.x;
    int itile = blockIdx.x, h = blockIdx.y, b = blockIdx.z;
    int i0 = itile * 64;
    int il = t & 63, sg = t >> 6;

    float acc[10];
    #pragma unroll
    for (int u = 0; u < 10; u++) acc[u] = 0.f;

    for (int jtt = 0; jtt < 8; jtt++) {
        int j0 = jtt * 64;
        for (int idx = t; idx < 4096; idx += 256) {
            int rr = idx >> 6, cc = idx & 63;
            A_s[rr][cc] = d_apre[(((size_t)(b*512 + i0 + rr))*12 + h)*512 + j0 + cc];
        }
        for (int idx = t; idx < 2560; idx += 256) {
            int jj = idx / 40, ss = idx % 40;
            int tok = b*512 + j0 + jj;
            Vt_s[jj][ss] = (ss < 16) ? d_v[tok*192 + h*16 + ss]
                                     : d_vg[tok*288 + h*24 + (ss-16)];
        }
        __syncthreads();
        #pragma unroll 4
        for (int jj = 0; jj < 64; jj++) {
            float a = A_s[il][jj];
            #pragma unroll
            for (int u = 0; u < 10; u++) acc[u] += a * Vt_s[jj][sg*10 + u];
        }
        __syncthreads();
    }
    int tok = b*512 + i0 + il;
    #pragma unroll
    for (int u = 0; u < 10; u++) {
        int ss = sg*10 + u;
        if (ss < 16) d_o  [tok*192 + h*16 + ss]      = acc[u];
        else         d_opt[tok*288 + h*24 + (ss-16)] = acc[u];
    }
}

// ---------------------------------------------------------------------------
// Kernel 7: local transform + dists + final GEMM (16 tokens per block)
// ---------------------------------------------------------------------------
__global__ void final_kernel(
    const float* __restrict__ rot, const float* __restrict__ trans,
    const float* __restrict__ Wout, const float* __restrict__ bout,
    float* __restrict__ out_s)
{
    __shared__ float feats[16][577];
    int t = threadIdx.x;
    int tok0 = blockIdx.x * 16;

    for (int idx = t; idx < 16*192; idx += 256) {
        int tt = idx / 192, cc = idx % 192;
        feats[tt][cc] = d_o[(tok0+tt)*192 + cc];
    }
    for (int idx = t; idx < 16*96; idx += 256) {
        int tt = idx / 96, pp = idx % 96;
        int tok = tok0 + tt;
        float px = d_opt[tok*288 + pp*3 + 0] - trans[tok*3+0]*SCALEF;
        float py = d_opt[tok*288 + pp*3 + 1] - trans[tok*3+1]*SCALEF;
        float pz = d_opt[tok*288 + pp*3 + 2] - trans[tok*3+2]*SCALEF;
        const float* R = rot + tok*9;
        float lx = R[0]*px + R[3]*py + R[6]*pz;
        float ly = R[1]*px + R[4]*py + R[7]*pz;
        float lz = R[2]*px + R[5]*py + R[8]*pz;
        float d  = sqrtf(lx*lx + ly*ly + lz*lz + 1e-8f);
        feats[tt][192 + pp] = lx;
        feats[tt][288 + pp] = ly;
        feats[tt][384 + pp] = lz;
        feats[tt][480 + pp] = d;
    }
    __syncthreads();

    for (int o = t; o < 384; o += 256) {
        float acc[16];
        float bv = bout[o];
        #pragma unroll
        for (int tt = 0; tt < 16; tt++) acc[tt] = bv;
        for (int kk = 0; kk < 576; kk++) {
            float w = Wout[kk*384 + o];
            #pragma unroll
            for (int tt = 0; tt < 16; tt++) acc[tt] += feats[tt][kk] * w;
        }
        #pragma unroll
        for (int tt = 0; tt < 16; tt++) out_s[(size_t)(tok0+tt)*384 + o] = acc[tt];
    }
}

// ---------------------------------------------------------------------------
// launch
// ---------------------------------------------------------------------------
extern "C" void kernel_launch(void* const* d_in, const int* in_sizes, int n_in,
                              void* d_out, int out_size)
{
    const float* s     = (const float*)d_in[0];
    const float* rot   = (const float*)d_in[1];
    const float* trans = (const float*)d_in[2];
    const float* mask  = (const float*)d_in[3];
    const float* Wq    = (const float*)d_in[4];
    const float* bq    = (const float*)d_in[5];
    const float* Wkv   = (const float*)d_in[6];
    const float* bkv   = (const float*)d_in[7];
    const float* hwts  = (const float*)d_in[8];
    const float* ln_g  = (const float*)d_in[9];
    const float* ln_b  = (const float*)d_in[10];
    const float* Wpq   = (const float*)d_in[11];
    const float* bpq   = (const float*)d_in[12];
    const float* Wpv   = (const float*)d_in[13];
    const float* bpv   = (const float*)d_in[14];
    const float* Wvl   = (const float*)d_in[15];
    const float* gm    = (const float*)d_in[16];
    const float* gs    = (const float*)d_in[17];
    const float* Wg    = (const float*)d_in[18];
    const float* bg    = (const float*)d_in[19];
    const float* W1    = (const float*)d_in[20];
    const float* b1    = (const float*)d_in[21];
    const float* W2    = (const float*)d_in[22];
    const float* b2    = (const float*)d_in[23];
    const float* Wkvp  = (const float*)d_in[24];
    const float* bkvp  = (const float*)d_in[25];
    const float* Wout  = (const float*)d_in[26];
    const float* bout  = (const float*)d_in[27];

    float* out   = (float*)d_out;
    float* out_s = out;                                   // (B,N,CS)
    float* out_g = out + (size_t)Bc*Nc*CSc;               // (B,N,N,G)

    tok_kernel<<<NTOK/8, 256>>>(s, ln_g, ln_b, Wq, bq, Wkv, bkv,
                                Wpq, bpq, Wpv, bpv, Wkvp, bkvp);
    vg_kernel<<<(NTOK*96 + 255)/256, 256>>>(rot, trans);
    qk_kernel<<<dim3(8, 12, 2), 256>>>();

    cudaFuncSetAttribute(pair_kernel, cudaFuncAttributeMaxDynamicSharedMemorySize,
                         PAIR_SMEM_BYTES);
    pair_kernel<<<NTOK, 256, PAIR_SMEM_BYTES>>>(rot, trans, mask, hwts, Wvl, gm, gs,
                                                Wg, bg, W1, b1, W2, b2, out_g);
    softmax_kernel<<<NTOK, 128>>>();
    av_kernel<<<dim3(8, 12, 2), 256>>>();
    final_kernel<<<NTOK/16, 256>>>(rot, trans, Wout, bout, out_s);
}